// round 1
// baseline (speedup 1.0000x reference)
#include <cuda_runtime.h>
#include <math.h>

#define B_   8
#define T_   12
#define N_   307
#define D_   512
#define H_   8
#define HD_  64
#define M_TOT (B_*T_*N_)   // 29472

// ---------------- device scratch (allocation-free rule) ----------------
__device__ float g_mask[N_*N_];
__device__ float g_q[M_TOT*D_];
__device__ float g_k[M_TOT*D_];
__device__ float g_v[M_TOT*D_];
__device__ float g_attn[M_TOT*D_];

// ---------------- mask = row-softmax(semantic_matrix) ----------------
__global__ void mask_softmax_kernel(const float* __restrict__ sem,
                                    float* __restrict__ mask)
{
    int row = blockIdx.x;
    int tid = threadIdx.x;
    __shared__ float red[256];
    const float* x = sem + (size_t)row * N_;
    float v0 = (tid       < N_) ? x[tid]       : -INFINITY;
    float v1 = (tid + 256 < N_) ? x[tid + 256] : -INFINITY;
    red[tid] = fmaxf(v0, v1);
    __syncthreads();
    for (int s = 128; s > 0; s >>= 1) {
        if (tid < s) red[tid] = fmaxf(red[tid], red[tid + s]);
        __syncthreads();
    }
    float rowmax = red[0];
    __syncthreads();
    float e0 = (tid       < N_) ? __expf(v0 - rowmax) : 0.f;
    float e1 = (tid + 256 < N_) ? __expf(v1 - rowmax) : 0.f;
    red[tid] = e0 + e1;
    __syncthreads();
    for (int s = 128; s > 0; s >>= 1) {
        if (tid < s) red[tid] += red[tid + s];
        __syncthreads();
    }
    float inv = 1.f / red[0];
    if (tid       < N_) mask[(size_t)row * N_ + tid]       = e0 * inv;
    if (tid + 256 < N_) mask[(size_t)row * N_ + tid + 256] = e1 * inv;
}

// ---------------- C[M,512] = A[M,512] @ W[512,512] + bias ----------------
#define BM 128
#define BN 128
#define BK 16

__global__ __launch_bounds__(256)
void gemm_bias_kernel(const float* __restrict__ A, const float* __restrict__ W,
                      const float* __restrict__ bias, float* __restrict__ C,
                      int M)
{
    __shared__ float As[BK][BM + 4];   // transposed A tile, padded
    __shared__ float Ws[BK][BN];
    int tid = threadIdx.x;
    int m0  = blockIdx.y * BM;
    int n0  = blockIdx.x * BN;
    int tm0 = (tid / 16) * 8;
    int tn0 = (tid % 16) * 8;

    float acc[8][8];
    #pragma unroll
    for (int i = 0; i < 8; i++)
        #pragma unroll
        for (int j = 0; j < 8; j++) acc[i][j] = 0.f;

    for (int k0 = 0; k0 < D_; k0 += BK) {
        // load A tile 128x16 (transpose into smem)
        #pragma unroll
        for (int r = 0; r < 2; r++) {
            int e  = tid + r * 256;          // 0..511
            int am = e >> 2;
            int ak = (e & 3) * 4;
            float4 val = make_float4(0.f, 0.f, 0.f, 0.f);
            int gm = m0 + am;
            if (gm < M) val = *(const float4*)(A + (size_t)gm * D_ + k0 + ak);
            As[ak + 0][am] = val.x; As[ak + 1][am] = val.y;
            As[ak + 2][am] = val.z; As[ak + 3][am] = val.w;
        }
        // load W tile 16x128
        #pragma unroll
        for (int r = 0; r < 2; r++) {
            int e  = tid + r * 256;
            int wk = e >> 5;
            int wn = (e & 31) * 4;
            *(float4*)&Ws[wk][wn] =
                *(const float4*)(W + (size_t)(k0 + wk) * D_ + n0 + wn);
        }
        __syncthreads();
        #pragma unroll
        for (int kk = 0; kk < BK; kk++) {
            float a[8], b[8];
            *(float4*)&a[0] = *(const float4*)&As[kk][tm0];
            *(float4*)&a[4] = *(const float4*)&As[kk][tm0 + 4];
            *(float4*)&b[0] = *(const float4*)&Ws[kk][tn0];
            *(float4*)&b[4] = *(const float4*)&Ws[kk][tn0 + 4];
            #pragma unroll
            for (int i = 0; i < 8; i++)
                #pragma unroll
                for (int j = 0; j < 8; j++) acc[i][j] += a[i] * b[j];
        }
        __syncthreads();
    }

    #pragma unroll
    for (int i = 0; i < 8; i++) {
        int gm = m0 + tm0 + i;
        if (gm >= M) continue;
        #pragma unroll
        for (int j = 0; j < 8; j += 4) {
            float4 o;
            o.x = acc[i][j + 0] + bias[n0 + tn0 + j + 0];
            o.y = acc[i][j + 1] + bias[n0 + tn0 + j + 1];
            o.z = acc[i][j + 2] + bias[n0 + tn0 + j + 2];
            o.w = acc[i][j + 3] + bias[n0 + tn0 + j + 3];
            *(float4*)(C + (size_t)gm * D_ + n0 + tn0 + j) = o;
        }
    }
}

// ---------------- fused attention with multiplicative mask ----------------
// grid: (5 q-tiles, B*T*H). block = 256 threads (16x16), each thread 4x4.
__global__ __launch_bounds__(256)
void attn_kernel(const float* __restrict__ q, const float* __restrict__ k,
                 const float* __restrict__ v, const float* __restrict__ mask,
                 float* __restrict__ out)
{
    __shared__ float Qts[64 * 64];  // [d][n]  (transposed Q tile)
    __shared__ float KV [64 * 64];  // K as [d][m], then reused as V [m][d]
    __shared__ float Ps [64 * 64];  // [n][m]  probabilities

    int tid = threadIdx.x;
    int bth = blockIdx.y;          // (b*T+t)*H + h
    int bt  = bth / H_;
    int h   = bth % H_;
    int n0  = blockIdx.x * 64;
    size_t base = (size_t)bt * N_ * D_ + (size_t)h * HD_;

    int tx = tid & 15, ty = tid >> 4;
    int tm0 = ty * 4, tn0 = tx * 4;
    const float scale = 0.125f;    // 1/sqrt(64)

    // load Q tile transposed
    #pragma unroll
    for (int r = 0; r < 4; r++) {
        int e   = tid + r * 256;       // 0..1023
        int row = e >> 4;              // 0..63
        int d4  = (e & 15) * 4;
        float4 val = make_float4(0.f, 0.f, 0.f, 0.f);
        int gn = n0 + row;
        if (gn < N_) val = *(const float4*)(q + base + (size_t)gn * D_ + d4);
        Qts[(d4 + 0) * 64 + row] = val.x; Qts[(d4 + 1) * 64 + row] = val.y;
        Qts[(d4 + 2) * 64 + row] = val.z; Qts[(d4 + 3) * 64 + row] = val.w;
    }

    float acc[4][4];
    float rm[4], rs[4];
    #pragma unroll
    for (int u = 0; u < 4; u++) {
        rm[u] = -INFINITY; rs[u] = 0.f;
        #pragma unroll
        for (int w = 0; w < 4; w++) acc[u][w] = 0.f;
    }

    for (int m0 = 0; m0 < N_; m0 += 64) {
        // load K tile transposed into KV: Kts[d][m]
        #pragma unroll
        for (int r = 0; r < 4; r++) {
            int e   = tid + r * 256;
            int row = e >> 4;
            int d4  = (e & 15) * 4;
            float4 val = make_float4(0.f, 0.f, 0.f, 0.f);
            int gm = m0 + row;
            if (gm < N_) val = *(const float4*)(k + base + (size_t)gm * D_ + d4);
            KV[(d4 + 0) * 64 + row] = val.x; KV[(d4 + 1) * 64 + row] = val.y;
            KV[(d4 + 2) * 64 + row] = val.z; KV[(d4 + 3) * 64 + row] = val.w;
        }
        __syncthreads();

        // S = Q @ K^T
        float s[4][4];
        #pragma unroll
        for (int u = 0; u < 4; u++)
            #pragma unroll
            for (int j = 0; j < 4; j++) s[u][j] = 0.f;
        #pragma unroll
        for (int kk = 0; kk < HD_; kk++) {
            float a[4], b[4];
            *(float4*)a = *(const float4*)&Qts[kk * 64 + tm0];
            *(float4*)b = *(const float4*)&KV [kk * 64 + tn0];
            #pragma unroll
            for (int u = 0; u < 4; u++)
                #pragma unroll
                for (int j = 0; j < 4; j++) s[u][j] += a[u] * b[j];
        }

        // multiplicative mask + scale; OOB m-cols -> -inf
        #pragma unroll
        for (int u = 0; u < 4; u++) {
            int gn   = n0 + tm0 + u;
            int nrow = (gn < N_) ? gn : 0;
            #pragma unroll
            for (int j = 0; j < 4; j++) {
                int gm = m0 + tn0 + j;
                if (gm < N_)
                    s[u][j] = s[u][j] * scale * mask[(size_t)nrow * N_ + gm];
                else
                    s[u][j] = -INFINITY;
            }
        }

        // online softmax (row reduction across the 16 tx-lanes)
        #pragma unroll
        for (int u = 0; u < 4; u++) {
            float tmax = fmaxf(fmaxf(s[u][0], s[u][1]), fmaxf(s[u][2], s[u][3]));
            #pragma unroll
            for (int o = 8; o > 0; o >>= 1)
                tmax = fmaxf(tmax, __shfl_xor_sync(0xffffffffu, tmax, o));
            float newm   = fmaxf(rm[u], tmax);     // always finite
            float factor = __expf(rm[u] - newm);
            float tsum   = 0.f;
            #pragma unroll
            for (int j = 0; j < 4; j++) {
                s[u][j] = __expf(s[u][j] - newm);
                tsum += s[u][j];
            }
            #pragma unroll
            for (int o = 8; o > 0; o >>= 1)
                tsum += __shfl_xor_sync(0xffffffffu, tsum, o);
            rs[u] = rs[u] * factor + tsum;
            rm[u] = newm;
            #pragma unroll
            for (int w = 0; w < 4; w++) acc[u][w] *= factor;
            #pragma unroll
            for (int j = 0; j < 4; j++) Ps[(tm0 + u) * 64 + tn0 + j] = s[u][j];
        }
        __syncthreads();   // Kts reads done, Ps visible

        // load V tile into KV (natural layout [m][d]); zero-fill OOB rows
        #pragma unroll
        for (int r = 0; r < 4; r++) {
            int e   = tid + r * 256;
            int row = e >> 4;
            int d4  = (e & 15) * 4;
            float4 val = make_float4(0.f, 0.f, 0.f, 0.f);
            int gm = m0 + row;
            if (gm < N_) val = *(const float4*)(v + base + (size_t)gm * D_ + d4);
            *(float4*)&KV[row * 64 + d4] = val;
        }
        __syncthreads();

        // acc += P @ V
        #pragma unroll 8
        for (int kk = 0; kk < 64; kk++) {
            float a[4], b[4];
            #pragma unroll
            for (int u = 0; u < 4; u++) a[u] = Ps[(tm0 + u) * 64 + kk];
            *(float4*)b = *(const float4*)&KV[kk * 64 + tn0];
            #pragma unroll
            for (int u = 0; u < 4; u++)
                #pragma unroll
                for (int w = 0; w < 4; w++) acc[u][w] += a[u] * b[w];
        }
        __syncthreads();   // protect KV/Ps before next tile overwrite
    }

    // epilogue: normalize and store
    #pragma unroll
    for (int u = 0; u < 4; u++) {
        int gn = n0 + tm0 + u;
        if (gn >= N_) continue;
        float inv = 1.f / rs[u];
        float4 o;
        o.x = acc[u][0] * inv; o.y = acc[u][1] * inv;
        o.z = acc[u][2] * inv; o.w = acc[u][3] * inv;
        *(float4*)(out + base + (size_t)gn * D_ + tn0) = o;
    }
}

// ---------------- launch ----------------
extern "C" void kernel_launch(void* const* d_in, const int* in_sizes, int n_in,
                              void* d_out, int out_size)
{
    const float* query = (const float*)d_in[0];
    const float* key   = (const float*)d_in[1];
    const float* value = (const float*)d_in[2];
    const float* sem   = (const float*)d_in[3];
    const float* Wq    = (const float*)d_in[4];
    const float* bq    = (const float*)d_in[5];
    const float* Wk    = (const float*)d_in[6];
    const float* bk    = (const float*)d_in[7];
    const float* Wv    = (const float*)d_in[8];
    const float* bv    = (const float*)d_in[9];
    const float* Wo    = (const float*)d_in[10];
    const float* bo    = (const float*)d_in[11];
    float* out = (float*)d_out;

    float *mask_p, *q_p, *k_p, *v_p, *attn_p;
    cudaGetSymbolAddress((void**)&mask_p, g_mask);
    cudaGetSymbolAddress((void**)&q_p,    g_q);
    cudaGetSymbolAddress((void**)&k_p,    g_k);
    cudaGetSymbolAddress((void**)&v_p,    g_v);
    cudaGetSymbolAddress((void**)&attn_p, g_attn);

    mask_softmax_kernel<<<N_, 256>>>(sem, mask_p);

    dim3 gg(D_ / BN, (M_TOT + BM - 1) / BM);
    gemm_bias_kernel<<<gg, 256>>>(query, Wq, bq, q_p, M_TOT);
    gemm_bias_kernel<<<gg, 256>>>(key,   Wk, bk, k_p, M_TOT);
    gemm_bias_kernel<<<gg, 256>>>(value, Wv, bv, v_p, M_TOT);

    dim3 ga((N_ + 63) / 64, B_ * T_ * H_);
    attn_kernel<<<ga, 256>>>(q_p, k_p, v_p, mask_p, attn_p);

    gemm_bias_kernel<<<gg, 256>>>(attn_p, Wo, bo, out, M_TOT);
}

// round 2
// speedup vs baseline: 3.0507x; 3.0507x over previous
#include <cuda_runtime.h>
#include <math.h>
#include <cstdint>

#define B_   8
#define T_   12
#define N_   307
#define D_   512
#define H_   8
#define HD_  64
#define M_TOT (B_*T_*N_)   // 29472

// ---------------- device scratch (allocation-free rule) ----------------
__device__ float g_mask[N_*N_];
__device__ float g_q[M_TOT*D_];
__device__ float g_k[M_TOT*D_];
__device__ float g_v[M_TOT*D_];
__device__ float g_attn[M_TOT*D_];

__device__ __forceinline__ uint32_t f2tf32(float x) {
    uint32_t y;
    asm("cvt.rna.tf32.f32 %0, %1;" : "=r"(y) : "f"(x));
    return y;
}

// ---------------- mask = row-softmax(semantic_matrix) ----------------
__global__ void mask_softmax_kernel(const float* __restrict__ sem,
                                    float* __restrict__ mask)
{
    int row = blockIdx.x;
    int tid = threadIdx.x;
    __shared__ float red[256];
    const float* x = sem + (size_t)row * N_;
    float v0 = (tid       < N_) ? x[tid]       : -INFINITY;
    float v1 = (tid + 256 < N_) ? x[tid + 256] : -INFINITY;
    red[tid] = fmaxf(v0, v1);
    __syncthreads();
    for (int s = 128; s > 0; s >>= 1) {
        if (tid < s) red[tid] = fmaxf(red[tid], red[tid + s]);
        __syncthreads();
    }
    float rowmax = red[0];
    __syncthreads();
    float e0 = (tid       < N_) ? __expf(v0 - rowmax) : 0.f;
    float e1 = (tid + 256 < N_) ? __expf(v1 - rowmax) : 0.f;
    red[tid] = e0 + e1;
    __syncthreads();
    for (int s = 128; s > 0; s >>= 1) {
        if (tid < s) red[tid] += red[tid + s];
        __syncthreads();
    }
    float inv = 1.f / red[0];
    if (tid       < N_) mask[(size_t)row * N_ + tid]       = e0 * inv;
    if (tid + 256 < N_) mask[(size_t)row * N_ + tid + 256] = e1 * inv;
}

// ---------------- tf32 tensor-core GEMM: C[M,512] = A @ W + bias --------
// tiles: 128x128x32, 256 threads = 8 warps (2 m x 4 n), warp tile 64x32.
// mma.sync.aligned.m16n8k8.row.col.f32.tf32.tf32.f32
__global__ __launch_bounds__(256)
void gemm_bias_tf32_kernel(const float* __restrict__ A, const float* __restrict__ W,
                           const float* __restrict__ bias, float* __restrict__ C,
                           int M)
{
    __shared__ float As[128][36];   // [m][k], pad 36 -> ldmatrix conflict-free
    __shared__ float Ws[32][132];   // [k][n]

    int tid  = threadIdx.x;
    int lane = tid & 31;
    int wid  = tid >> 5;
    int warp_m = wid & 1;           // 0..1
    int warp_n = wid >> 1;          // 0..3
    int m0 = blockIdx.y * 128;
    int n0 = blockIdx.x * 128;

    float acc[4][4][4];
    #pragma unroll
    for (int mi = 0; mi < 4; mi++)
        #pragma unroll
        for (int ni = 0; ni < 4; ni++)
            #pragma unroll
            for (int r = 0; r < 4; r++) acc[mi][ni][r] = 0.f;

    float4 stA[4], stW[4];

    // ---- stage k-tile k0 into registers ----
    auto ldg_tile = [&](int k0) {
        #pragma unroll
        for (int r = 0; r < 4; r++) {
            int e  = tid + r * 256;          // 0..1023
            int am = e >> 3;                 // 0..127
            int ak = (e & 7) * 4;            // 0..28
            int gm = m0 + am;
            stA[r] = (gm < M) ? *(const float4*)(A + (size_t)gm * D_ + k0 + ak)
                              : make_float4(0.f, 0.f, 0.f, 0.f);
        }
        #pragma unroll
        for (int r = 0; r < 4; r++) {
            int e  = tid + r * 256;
            int wk = e >> 5;                 // 0..31
            int wn = (e & 31) * 4;           // 0..124
            stW[r] = *(const float4*)(W + (size_t)(k0 + wk) * D_ + n0 + wn);
        }
    };
    // ---- registers -> smem (with tf32 rounding) ----
    auto sts_tile = [&]() {
        #pragma unroll
        for (int r = 0; r < 4; r++) {
            int e  = tid + r * 256;
            int am = e >> 3;
            int ak = (e & 7) * 4;
            uint4 v;
            v.x = f2tf32(stA[r].x); v.y = f2tf32(stA[r].y);
            v.z = f2tf32(stA[r].z); v.w = f2tf32(stA[r].w);
            *(uint4*)&As[am][ak] = v;
        }
        #pragma unroll
        for (int r = 0; r < 4; r++) {
            int e  = tid + r * 256;
            int wk = e >> 5;
            int wn = (e & 31) * 4;
            uint4 v;
            v.x = f2tf32(stW[r].x); v.y = f2tf32(stW[r].y);
            v.z = f2tf32(stW[r].z); v.w = f2tf32(stW[r].w);
            *(uint4*)&Ws[wk][wn] = v;
        }
    };

    ldg_tile(0);
    sts_tile();
    __syncthreads();

    int mrow_base = warp_m * 64 + (lane & 7) + ((lane >> 3) & 1) * 8;
    int kcol_sub  = (lane >> 4) * 4;
    int bk_row    = lane & 3;
    int bn_col    = warp_n * 32 + (lane >> 2);

    for (int k0 = 0; k0 < D_; k0 += 32) {
        bool last = (k0 == D_ - 32);
        if (!last) ldg_tile(k0 + 32);

        #pragma unroll
        for (int kk = 0; kk < 4; kk++) {
            uint32_t a[4][4];
            #pragma unroll
            for (int mi = 0; mi < 4; mi++) {
                int m    = mrow_base + mi * 16;
                int kcol = kk * 8 + kcol_sub;
                uint32_t saddr = (uint32_t)__cvta_generic_to_shared(&As[m][kcol]);
                asm volatile(
                    "ldmatrix.sync.aligned.m8n8.x4.shared.b16 {%0,%1,%2,%3}, [%4];"
                    : "=r"(a[mi][0]), "=r"(a[mi][1]), "=r"(a[mi][2]), "=r"(a[mi][3])
                    : "r"(saddr));
            }
            #pragma unroll
            for (int ni = 0; ni < 4; ni++) {
                uint32_t b0 = __float_as_uint(Ws[kk * 8 + bk_row    ][bn_col + ni * 8]);
                uint32_t b1 = __float_as_uint(Ws[kk * 8 + bk_row + 4][bn_col + ni * 8]);
                #pragma unroll
                for (int mi = 0; mi < 4; mi++) {
                    asm volatile(
                        "mma.sync.aligned.m16n8k8.row.col.f32.tf32.tf32.f32 "
                        "{%0,%1,%2,%3}, {%4,%5,%6,%7}, {%8,%9}, {%0,%1,%2,%3};"
                        : "+f"(acc[mi][ni][0]), "+f"(acc[mi][ni][1]),
                          "+f"(acc[mi][ni][2]), "+f"(acc[mi][ni][3])
                        : "r"(a[mi][0]), "r"(a[mi][1]), "r"(a[mi][2]), "r"(a[mi][3]),
                          "r"(b0), "r"(b1));
                }
            }
        }
        __syncthreads();
        if (!last) {
            sts_tile();
            __syncthreads();
        }
    }

    // ---- epilogue: bias + store ----
    int crow = m0 + warp_m * 64 + (lane >> 2);
    int ccol0 = n0 + warp_n * 32 + 2 * (lane & 3);
    #pragma unroll
    for (int mi = 0; mi < 4; mi++) {
        int r0 = crow + mi * 16;
        #pragma unroll
        for (int ni = 0; ni < 4; ni++) {
            int cc = ccol0 + ni * 8;
            float b0 = bias[cc], b1 = bias[cc + 1];
            if (r0 < M) {
                float2 o = make_float2(acc[mi][ni][0] + b0, acc[mi][ni][1] + b1);
                *(float2*)(C + (size_t)r0 * D_ + cc) = o;
            }
            if (r0 + 8 < M) {
                float2 o = make_float2(acc[mi][ni][2] + b0, acc[mi][ni][3] + b1);
                *(float2*)(C + (size_t)(r0 + 8) * D_ + cc) = o;
            }
        }
    }
}

// ---------------- fused attention with multiplicative mask ----------------
__global__ __launch_bounds__(256)
void attn_kernel(const float* __restrict__ q, const float* __restrict__ k,
                 const float* __restrict__ v, const float* __restrict__ mask,
                 float* __restrict__ out)
{
    __shared__ float Qts[64 * 64];  // [d][n]  (transposed Q tile)
    __shared__ float KV [64 * 64];  // K as [d][m], then reused as V [m][d]
    __shared__ float Ps [64 * 64];  // [n][m]  probabilities

    int tid = threadIdx.x;
    int bth = blockIdx.y;          // (b*T+t)*H + h
    int bt  = bth / H_;
    int h   = bth % H_;
    int n0  = blockIdx.x * 64;
    size_t base = (size_t)bt * N_ * D_ + (size_t)h * HD_;

    int tx = tid & 15, ty = tid >> 4;
    int tm0 = ty * 4, tn0 = tx * 4;
    const float scale = 0.125f;    // 1/sqrt(64)

    #pragma unroll
    for (int r = 0; r < 4; r++) {
        int e   = tid + r * 256;
        int row = e >> 4;
        int d4  = (e & 15) * 4;
        float4 val = make_float4(0.f, 0.f, 0.f, 0.f);
        int gn = n0 + row;
        if (gn < N_) val = *(const float4*)(q + base + (size_t)gn * D_ + d4);
        Qts[(d4 + 0) * 64 + row] = val.x; Qts[(d4 + 1) * 64 + row] = val.y;
        Qts[(d4 + 2) * 64 + row] = val.z; Qts[(d4 + 3) * 64 + row] = val.w;
    }

    float acc[4][4];
    float rm[4], rs[4];
    #pragma unroll
    for (int u = 0; u < 4; u++) {
        rm[u] = -INFINITY; rs[u] = 0.f;
        #pragma unroll
        for (int w = 0; w < 4; w++) acc[u][w] = 0.f;
    }

    for (int m0 = 0; m0 < N_; m0 += 64) {
        #pragma unroll
        for (int r = 0; r < 4; r++) {
            int e   = tid + r * 256;
            int row = e >> 4;
            int d4  = (e & 15) * 4;
            float4 val = make_float4(0.f, 0.f, 0.f, 0.f);
            int gm = m0 + row;
            if (gm < N_) val = *(const float4*)(k + base + (size_t)gm * D_ + d4);
            KV[(d4 + 0) * 64 + row] = val.x; KV[(d4 + 1) * 64 + row] = val.y;
            KV[(d4 + 2) * 64 + row] = val.z; KV[(d4 + 3) * 64 + row] = val.w;
        }
        __syncthreads();

        float s[4][4];
        #pragma unroll
        for (int u = 0; u < 4; u++)
            #pragma unroll
            for (int j = 0; j < 4; j++) s[u][j] = 0.f;
        #pragma unroll
        for (int kk = 0; kk < HD_; kk++) {
            float a[4], b[4];
            *(float4*)a = *(const float4*)&Qts[kk * 64 + tm0];
            *(float4*)b = *(const float4*)&KV [kk * 64 + tn0];
            #pragma unroll
            for (int u = 0; u < 4; u++)
                #pragma unroll
                for (int j = 0; j < 4; j++) s[u][j] += a[u] * b[j];
        }

        #pragma unroll
        for (int u = 0; u < 4; u++) {
            int gn   = n0 + tm0 + u;
            int nrow = (gn < N_) ? gn : 0;
            #pragma unroll
            for (int j = 0; j < 4; j++) {
                int gm = m0 + tn0 + j;
                if (gm < N_)
                    s[u][j] = s[u][j] * scale * mask[(size_t)nrow * N_ + gm];
                else
                    s[u][j] = -INFINITY;
            }
        }

        #pragma unroll
        for (int u = 0; u < 4; u++) {
            float tmax = fmaxf(fmaxf(s[u][0], s[u][1]), fmaxf(s[u][2], s[u][3]));
            #pragma unroll
            for (int o = 8; o > 0; o >>= 1)
                tmax = fmaxf(tmax, __shfl_xor_sync(0xffffffffu, tmax, o));
            float newm   = fmaxf(rm[u], tmax);
            float factor = __expf(rm[u] - newm);
            float tsum   = 0.f;
            #pragma unroll
            for (int j = 0; j < 4; j++) {
                s[u][j] = __expf(s[u][j] - newm);
                tsum += s[u][j];
            }
            #pragma unroll
            for (int o = 8; o > 0; o >>= 1)
                tsum += __shfl_xor_sync(0xffffffffu, tsum, o);
            rs[u] = rs[u] * factor + tsum;
            rm[u] = newm;
            #pragma unroll
            for (int w = 0; w < 4; w++) acc[u][w] *= factor;
            #pragma unroll
            for (int j = 0; j < 4; j++) Ps[(tm0 + u) * 64 + tn0 + j] = s[u][j];
        }
        __syncthreads();

        #pragma unroll
        for (int r = 0; r < 4; r++) {
            int e   = tid + r * 256;
            int row = e >> 4;
            int d4  = (e & 15) * 4;
            float4 val = make_float4(0.f, 0.f, 0.f, 0.f);
            int gm = m0 + row;
            if (gm < N_) val = *(const float4*)(v + base + (size_t)gm * D_ + d4);
            *(float4*)&KV[row * 64 + d4] = val;
        }
        __syncthreads();

        #pragma unroll 8
        for (int kk = 0; kk < 64; kk++) {
            float a[4], b[4];
            #pragma unroll
            for (int u = 0; u < 4; u++) a[u] = Ps[(tm0 + u) * 64 + kk];
            *(float4*)b = *(const float4*)&KV[kk * 64 + tn0];
            #pragma unroll
            for (int u = 0; u < 4; u++)
                #pragma unroll
                for (int w = 0; w < 4; w++) acc[u][w] += a[u] * b[w];
        }
        __syncthreads();
    }

    #pragma unroll
    for (int u = 0; u < 4; u++) {
        int gn = n0 + tm0 + u;
        if (gn >= N_) continue;
        float inv = 1.f / rs[u];
        float4 o;
        o.x = acc[u][0] * inv; o.y = acc[u][1] * inv;
        o.z = acc[u][2] * inv; o.w = acc[u][3] * inv;
        *(float4*)(out + base + (size_t)gn * D_ + tn0) = o;
    }
}

// ---------------- launch ----------------
extern "C" void kernel_launch(void* const* d_in, const int* in_sizes, int n_in,
                              void* d_out, int out_size)
{
    const float* query = (const float*)d_in[0];
    const float* key   = (const float*)d_in[1];
    const float* value = (const float*)d_in[2];
    const float* sem   = (const float*)d_in[3];
    const float* Wq    = (const float*)d_in[4];
    const float* bq    = (const float*)d_in[5];
    const float* Wk    = (const float*)d_in[6];
    const float* bk    = (const float*)d_in[7];
    const float* Wv    = (const float*)d_in[8];
    const float* bv    = (const float*)d_in[9];
    const float* Wo    = (const float*)d_in[10];
    const float* bo    = (const float*)d_in[11];
    float* out = (float*)d_out;

    float *mask_p, *q_p, *k_p, *v_p, *attn_p;
    cudaGetSymbolAddress((void**)&mask_p, g_mask);
    cudaGetSymbolAddress((void**)&q_p,    g_q);
    cudaGetSymbolAddress((void**)&k_p,    g_k);
    cudaGetSymbolAddress((void**)&v_p,    g_v);
    cudaGetSymbolAddress((void**)&attn_p, g_attn);

    mask_softmax_kernel<<<N_, 256>>>(sem, mask_p);

    dim3 gg(D_ / 128, (M_TOT + 127) / 128);
    gemm_bias_tf32_kernel<<<gg, 256>>>(query, Wq, bq, q_p, M_TOT);
    gemm_bias_tf32_kernel<<<gg, 256>>>(key,   Wk, bk, k_p, M_TOT);
    gemm_bias_tf32_kernel<<<gg, 256>>>(value, Wv, bv, v_p, M_TOT);

    dim3 ga((N_ + 63) / 64, B_ * T_ * H_);
    attn_kernel<<<ga, 256>>>(q_p, k_p, v_p, mask_p, attn_p);

    gemm_bias_tf32_kernel<<<gg, 256>>>(attn_p, Wo, bo, out, M_TOT);
}

// round 3
// speedup vs baseline: 4.0867x; 1.3396x over previous
#include <cuda_runtime.h>
#include <math.h>
#include <cstdint>

#define B_   8
#define T_   12
#define N_   307
#define D_   512
#define H_   8
#define HD_  64
#define M_TOT (B_*T_*N_)   // 29472

// ---------------- device scratch (allocation-free rule) ----------------
__device__ float g_mask[N_*N_];
__device__ float g_q[M_TOT*D_];
__device__ float g_k[M_TOT*D_];
__device__ float g_v[M_TOT*D_];
__device__ float g_attn[M_TOT*D_];

__device__ __forceinline__ uint32_t f2tf32(float x) {
    uint32_t y;
    asm("cvt.rna.tf32.f32 %0, %1;" : "=r"(y) : "f"(x));
    return y;
}

// ---------------- mask = row-softmax(semantic_matrix) ----------------
__global__ void mask_softmax_kernel(const float* __restrict__ sem,
                                    float* __restrict__ mask)
{
    int row = blockIdx.x;
    int tid = threadIdx.x;
    __shared__ float red[256];
    const float* x = sem + (size_t)row * N_;
    float v0 = (tid       < N_) ? x[tid]       : -INFINITY;
    float v1 = (tid + 256 < N_) ? x[tid + 256] : -INFINITY;
    red[tid] = fmaxf(v0, v1);
    __syncthreads();
    for (int s = 128; s > 0; s >>= 1) {
        if (tid < s) red[tid] = fmaxf(red[tid], red[tid + s]);
        __syncthreads();
    }
    float rowmax = red[0];
    __syncthreads();
    float e0 = (tid       < N_) ? __expf(v0 - rowmax) : 0.f;
    float e1 = (tid + 256 < N_) ? __expf(v1 - rowmax) : 0.f;
    red[tid] = e0 + e1;
    __syncthreads();
    for (int s = 128; s > 0; s >>= 1) {
        if (tid < s) red[tid] += red[tid + s];
        __syncthreads();
    }
    float inv = 1.f / red[0];
    if (tid       < N_) mask[(size_t)row * N_ + tid]       = e0 * inv;
    if (tid + 256 < N_) mask[(size_t)row * N_ + tid + 256] = e1 * inv;
}

// ---------------- tf32 tensor-core GEMM: C[M,512] = A @ W + bias --------
__global__ __launch_bounds__(256)
void gemm_bias_tf32_kernel(const float* __restrict__ A, const float* __restrict__ W,
                           const float* __restrict__ bias, float* __restrict__ C,
                           int M)
{
    __shared__ float As[128][36];   // [m][k], 36 floats = 9x16B (odd) -> ldmatrix ok
    __shared__ float Ws[32][136];   // [k][n], 136 mod 32 = 8 -> conflict-free B reads

    int tid  = threadIdx.x;
    int lane = tid & 31;
    int wid  = tid >> 5;
    int warp_m = wid & 1;
    int warp_n = wid >> 1;
    int m0 = blockIdx.y * 128;
    int n0 = blockIdx.x * 128;

    float acc[4][4][4];
    #pragma unroll
    for (int mi = 0; mi < 4; mi++)
        #pragma unroll
        for (int ni = 0; ni < 4; ni++)
            #pragma unroll
            for (int r = 0; r < 4; r++) acc[mi][ni][r] = 0.f;

    float4 stA[4], stW[4];

    auto ldg_tile = [&](int k0) {
        #pragma unroll
        for (int r = 0; r < 4; r++) {
            int e  = tid + r * 256;
            int am = e >> 3;
            int ak = (e & 7) * 4;
            int gm = m0 + am;
            stA[r] = (gm < M) ? *(const float4*)(A + (size_t)gm * D_ + k0 + ak)
                              : make_float4(0.f, 0.f, 0.f, 0.f);
        }
        #pragma unroll
        for (int r = 0; r < 4; r++) {
            int e  = tid + r * 256;
            int wk = e >> 5;
            int wn = (e & 31) * 4;
            stW[r] = *(const float4*)(W + (size_t)(k0 + wk) * D_ + n0 + wn);
        }
    };
    auto sts_tile = [&]() {
        #pragma unroll
        for (int r = 0; r < 4; r++) {
            int e  = tid + r * 256;
            int am = e >> 3;
            int ak = (e & 7) * 4;
            uint4 v;
            v.x = f2tf32(stA[r].x); v.y = f2tf32(stA[r].y);
            v.z = f2tf32(stA[r].z); v.w = f2tf32(stA[r].w);
            *(uint4*)&As[am][ak] = v;
        }
        #pragma unroll
        for (int r = 0; r < 4; r++) {
            int e  = tid + r * 256;
            int wk = e >> 5;
            int wn = (e & 31) * 4;
            uint4 v;
            v.x = f2tf32(stW[r].x); v.y = f2tf32(stW[r].y);
            v.z = f2tf32(stW[r].z); v.w = f2tf32(stW[r].w);
            *(uint4*)&Ws[wk][wn] = v;
        }
    };

    ldg_tile(0);
    sts_tile();
    __syncthreads();

    int mrow_base = warp_m * 64 + (lane & 7) + ((lane >> 3) & 1) * 8;
    int kcol_sub  = (lane >> 4) * 4;
    int bk_row    = lane & 3;
    int bn_col    = warp_n * 32 + (lane >> 2);

    for (int k0 = 0; k0 < D_; k0 += 32) {
        bool last = (k0 == D_ - 32);
        if (!last) ldg_tile(k0 + 32);

        #pragma unroll
        for (int kk = 0; kk < 4; kk++) {
            uint32_t a[4][4];
            #pragma unroll
            for (int mi = 0; mi < 4; mi++) {
                int m    = mrow_base + mi * 16;
                int kcol = kk * 8 + kcol_sub;
                uint32_t saddr = (uint32_t)__cvta_generic_to_shared(&As[m][kcol]);
                asm volatile(
                    "ldmatrix.sync.aligned.m8n8.x4.shared.b16 {%0,%1,%2,%3}, [%4];"
                    : "=r"(a[mi][0]), "=r"(a[mi][1]), "=r"(a[mi][2]), "=r"(a[mi][3])
                    : "r"(saddr));
            }
            #pragma unroll
            for (int ni = 0; ni < 4; ni++) {
                uint32_t b0 = __float_as_uint(Ws[kk * 8 + bk_row    ][bn_col + ni * 8]);
                uint32_t b1 = __float_as_uint(Ws[kk * 8 + bk_row + 4][bn_col + ni * 8]);
                #pragma unroll
                for (int mi = 0; mi < 4; mi++) {
                    asm volatile(
                        "mma.sync.aligned.m16n8k8.row.col.f32.tf32.tf32.f32 "
                        "{%0,%1,%2,%3}, {%4,%5,%6,%7}, {%8,%9}, {%0,%1,%2,%3};"
                        : "+f"(acc[mi][ni][0]), "+f"(acc[mi][ni][1]),
                          "+f"(acc[mi][ni][2]), "+f"(acc[mi][ni][3])
                        : "r"(a[mi][0]), "r"(a[mi][1]), "r"(a[mi][2]), "r"(a[mi][3]),
                          "r"(b0), "r"(b1));
                }
            }
        }
        __syncthreads();
        if (!last) {
            sts_tile();
            __syncthreads();
        }
    }

    int crow = m0 + warp_m * 64 + (lane >> 2);
    int ccol0 = n0 + warp_n * 32 + 2 * (lane & 3);
    #pragma unroll
    for (int mi = 0; mi < 4; mi++) {
        int r0 = crow + mi * 16;
        #pragma unroll
        for (int ni = 0; ni < 4; ni++) {
            int cc = ccol0 + ni * 8;
            float b0 = bias[cc], b1 = bias[cc + 1];
            if (r0 < M) {
                float2 o = make_float2(acc[mi][ni][0] + b0, acc[mi][ni][1] + b1);
                *(float2*)(C + (size_t)r0 * D_ + cc) = o;
            }
            if (r0 + 8 < M) {
                float2 o = make_float2(acc[mi][ni][2] + b0, acc[mi][ni][3] + b1);
                *(float2*)(C + (size_t)(r0 + 8) * D_ + cc) = o;
            }
        }
    }
}

// ---------------- tf32 tensor-core flash attention ----------------
// block = 128 thr / 4 warps. q-tile 64 rows. warp = m16 x n64.
// smem: Qs[64][68], Ps[64][68] (mask tile then P), KVs[64][72] (K then V, natural).
#define QP 68
#define KVP 72
#define ATTN_SMEM ((64*QP*2 + 64*KVP) * 4)   // 53248 bytes

__global__ __launch_bounds__(128)
void attn_mma_kernel(const float* __restrict__ q, const float* __restrict__ k,
                     const float* __restrict__ v, const float* __restrict__ mask,
                     float* __restrict__ out)
{
    extern __shared__ float sm[];
    float* Qs  = sm;                 // [64][QP]
    float* Ps  = sm + 64 * QP;       // [64][QP]
    float* KVs = sm + 2 * 64 * QP;   // [64][KVP]

    int tid  = threadIdx.x;
    int lane = tid & 31;
    int wid  = tid >> 5;             // 0..3
    int bth  = blockIdx.y;
    int bt   = bth / H_;
    int h    = bth % H_;
    int n0   = blockIdx.x * 64;
    size_t base = (size_t)bt * N_ * D_ + (size_t)h * HD_;

    // load Q tile [64 rows][64 d] natural, tf32
    #pragma unroll
    for (int r = 0; r < 8; r++) {
        int e   = tid + r * 128;     // 0..1023
        int row = e >> 4;
        int c4  = (e & 15) * 4;
        float4 val = make_float4(0.f, 0.f, 0.f, 0.f);
        int gn = n0 + row;
        if (gn < N_) val = *(const float4*)(q + base + (size_t)gn * D_ + c4);
        uint4 t;
        t.x = f2tf32(val.x); t.y = f2tf32(val.y);
        t.z = f2tf32(val.z); t.w = f2tf32(val.w);
        *(uint4*)&Qs[row * QP + c4] = t;
    }

    float oacc[8][4];
    #pragma unroll
    for (int ni = 0; ni < 8; ni++)
        #pragma unroll
        for (int r = 0; r < 4; r++) oacc[ni][r] = 0.f;
    float rm[2] = {-INFINITY, -INFINITY};
    float rs[2] = {0.f, 0.f};

    int qrow_frag = wid * 16 + (lane >> 2);                     // acc row (and +8)
    int mrow_base = wid * 16 + (lane & 7) + ((lane >> 3) & 1) * 8;  // ldmatrix row
    int kcol_sub  = (lane >> 4) * 4;
    int l2  = lane >> 2;     // 0..7
    int l4  = lane & 3;      // 0..3
    const float scale = 0.125f;

    for (int m0 = 0; m0 < 320; m0 += 64) {
        // K tile natural [kv][d], tf32
        #pragma unroll
        for (int r = 0; r < 8; r++) {
            int e    = tid + r * 128;
            int mrow = e >> 4;
            int d4   = (e & 15) * 4;
            float4 val = make_float4(0.f, 0.f, 0.f, 0.f);
            int gm = m0 + mrow;
            if (gm < N_) val = *(const float4*)(k + base + (size_t)gm * D_ + d4);
            uint4 t;
            t.x = f2tf32(val.x); t.y = f2tf32(val.y);
            t.z = f2tf32(val.z); t.w = f2tf32(val.w);
            *(uint4*)&KVs[mrow * KVP + d4] = t;
        }
        // mask tile [q-row][kv-col] into Ps, coalesced
        #pragma unroll
        for (int r = 0; r < 32; r++) {
            int e   = tid + r * 128;   // 0..4095
            int row = e >> 6;
            int col = e & 63;
            int gr = n0 + row, gc = m0 + col;
            float mv = 0.f;
            if (gr < N_ && gc < N_) mv = mask[(size_t)gr * N_ + gc];
            Ps[row * QP + col] = mv;
        }
        __syncthreads();

        // ---- S = Q @ K^T (tf32 mma) ----
        float sacc[8][4];
        #pragma unroll
        for (int ni = 0; ni < 8; ni++)
            #pragma unroll
            for (int r = 0; r < 4; r++) sacc[ni][r] = 0.f;
        #pragma unroll
        for (int kk = 0; kk < 8; kk++) {
            uint32_t a[4];
            uint32_t saddr = (uint32_t)__cvta_generic_to_shared(
                &Qs[mrow_base * QP + kk * 8 + kcol_sub]);
            asm volatile(
                "ldmatrix.sync.aligned.m8n8.x4.shared.b16 {%0,%1,%2,%3}, [%4];"
                : "=r"(a[0]), "=r"(a[1]), "=r"(a[2]), "=r"(a[3])
                : "r"(saddr));
            #pragma unroll
            for (int ni = 0; ni < 8; ni++) {
                // B[k=d][n=kv] = K[kv][d] -> conflict-free (8*l2 + l4)
                uint32_t b0 = __float_as_uint(KVs[(ni * 8 + l2) * KVP + kk * 8 + l4]);
                uint32_t b1 = __float_as_uint(KVs[(ni * 8 + l2) * KVP + kk * 8 + l4 + 4]);
                asm volatile(
                    "mma.sync.aligned.m16n8k8.row.col.f32.tf32.tf32.f32 "
                    "{%0,%1,%2,%3}, {%4,%5,%6,%7}, {%8,%9}, {%0,%1,%2,%3};"
                    : "+f"(sacc[ni][0]), "+f"(sacc[ni][1]),
                      "+f"(sacc[ni][2]), "+f"(sacc[ni][3])
                    : "r"(a[0]), "r"(a[1]), "r"(a[2]), "r"(a[3]),
                      "r"(b0), "r"(b1));
            }
        }

        // ---- mask * scale, online softmax, write P (tf32) ----
        #pragma unroll
        for (int u = 0; u < 2; u++) {
            int rloc = qrow_frag + u * 8;        // local row
            float vals[16];
            #pragma unroll
            for (int ni = 0; ni < 8; ni++) {
                int c0 = ni * 8 + 2 * l4;
                float mv0 = Ps[rloc * QP + c0];
                float mv1 = Ps[rloc * QP + c0 + 1];
                float x0 = sacc[ni][2 * u + 0] * scale * mv0;
                float x1 = sacc[ni][2 * u + 1] * scale * mv1;
                if (m0 + c0     >= N_) x0 = -INFINITY;
                if (m0 + c0 + 1 >= N_) x1 = -INFINITY;
                vals[2 * ni]     = x0;
                vals[2 * ni + 1] = x1;
            }
            float tmax = vals[0];
            #pragma unroll
            for (int i = 1; i < 16; i++) tmax = fmaxf(tmax, vals[i]);
            tmax = fmaxf(tmax, __shfl_xor_sync(0xffffffffu, tmax, 1));
            tmax = fmaxf(tmax, __shfl_xor_sync(0xffffffffu, tmax, 2));
            float newm   = fmaxf(rm[u], tmax);
            float factor = __expf(rm[u] - newm);
            float tsum = 0.f;
            #pragma unroll
            for (int i = 0; i < 16; i++) {
                vals[i] = __expf(vals[i] - newm);
                tsum += vals[i];
            }
            tsum += __shfl_xor_sync(0xffffffffu, tsum, 1);
            tsum += __shfl_xor_sync(0xffffffffu, tsum, 2);
            rs[u] = rs[u] * factor + tsum;
            rm[u] = newm;
            #pragma unroll
            for (int ni = 0; ni < 8; ni++) {
                oacc[ni][2 * u]     *= factor;
                oacc[ni][2 * u + 1] *= factor;
                int c0 = ni * 8 + 2 * l4;
                Ps[rloc * QP + c0]     = __uint_as_float(f2tf32(vals[2 * ni]));
                Ps[rloc * QP + c0 + 1] = __uint_as_float(f2tf32(vals[2 * ni + 1]));
            }
        }
        __syncthreads();   // K reads + mask reads done; P visible

        // V tile natural [kv][d], tf32 (overwrites K)
        #pragma unroll
        for (int r = 0; r < 8; r++) {
            int e    = tid + r * 128;
            int mrow = e >> 4;
            int d4   = (e & 15) * 4;
            float4 val = make_float4(0.f, 0.f, 0.f, 0.f);
            int gm = m0 + mrow;
            if (gm < N_) val = *(const float4*)(v + base + (size_t)gm * D_ + d4);
            uint4 t;
            t.x = f2tf32(val.x); t.y = f2tf32(val.y);
            t.z = f2tf32(val.z); t.w = f2tf32(val.w);
            *(uint4*)&KVs[mrow * KVP + d4] = t;
        }
        __syncthreads();

        // ---- O += P @ V ----
        #pragma unroll
        for (int kk = 0; kk < 8; kk++) {
            uint32_t a[4];
            uint32_t saddr = (uint32_t)__cvta_generic_to_shared(
                &Ps[mrow_base * QP + kk * 8 + kcol_sub]);
            asm volatile(
                "ldmatrix.sync.aligned.m8n8.x4.shared.b16 {%0,%1,%2,%3}, [%4];"
                : "=r"(a[0]), "=r"(a[1]), "=r"(a[2]), "=r"(a[3])
                : "r"(saddr));
            #pragma unroll
            for (int ni = 0; ni < 8; ni++) {
                // B[k=kv][n=d] = V[kv][d] -> conflict-free (8*l4 + l2)
                uint32_t b0 = __float_as_uint(KVs[(kk * 8 + l4) * KVP + ni * 8 + l2]);
                uint32_t b1 = __float_as_uint(KVs[(kk * 8 + l4 + 4) * KVP + ni * 8 + l2]);
                asm volatile(
                    "mma.sync.aligned.m16n8k8.row.col.f32.tf32.tf32.f32 "
                    "{%0,%1,%2,%3}, {%4,%5,%6,%7}, {%8,%9}, {%0,%1,%2,%3};"
                    : "+f"(oacc[ni][0]), "+f"(oacc[ni][1]),
                      "+f"(oacc[ni][2]), "+f"(oacc[ni][3])
                    : "r"(a[0]), "r"(a[1]), "r"(a[2]), "r"(a[3]),
                      "r"(b0), "r"(b1));
            }
        }
        __syncthreads();   // protect KVs/Ps before next tile
    }

    // epilogue: normalize + store
    #pragma unroll
    for (int u = 0; u < 2; u++) {
        int gr = n0 + qrow_frag + u * 8;
        if (gr >= N_) continue;
        float inv = 1.f / rs[u];
        #pragma unroll
        for (int ni = 0; ni < 8; ni++) {
            int dc = ni * 8 + 2 * l4;
            float2 o = make_float2(oacc[ni][2 * u] * inv, oacc[ni][2 * u + 1] * inv);
            *(float2*)(out + base + (size_t)gr * D_ + dc) = o;
        }
    }
}

// ---------------- launch ----------------
extern "C" void kernel_launch(void* const* d_in, const int* in_sizes, int n_in,
                              void* d_out, int out_size)
{
    const float* query = (const float*)d_in[0];
    const float* key   = (const float*)d_in[1];
    const float* value = (const float*)d_in[2];
    const float* sem   = (const float*)d_in[3];
    const float* Wq    = (const float*)d_in[4];
    const float* bq    = (const float*)d_in[5];
    const float* Wk    = (const float*)d_in[6];
    const float* bk    = (const float*)d_in[7];
    const float* Wv    = (const float*)d_in[8];
    const float* bv    = (const float*)d_in[9];
    const float* Wo    = (const float*)d_in[10];
    const float* bo    = (const float*)d_in[11];
    float* out = (float*)d_out;

    float *mask_p, *q_p, *k_p, *v_p, *attn_p;
    cudaGetSymbolAddress((void**)&mask_p, g_mask);
    cudaGetSymbolAddress((void**)&q_p,    g_q);
    cudaGetSymbolAddress((void**)&k_p,    g_k);
    cudaGetSymbolAddress((void**)&v_p,    g_v);
    cudaGetSymbolAddress((void**)&attn_p, g_attn);

    static bool attr_set = false;
    if (!attr_set) {
        cudaFuncSetAttribute(attn_mma_kernel,
                             cudaFuncAttributeMaxDynamicSharedMemorySize, ATTN_SMEM);
        attr_set = true;
    }

    mask_softmax_kernel<<<N_, 256>>>(sem, mask_p);

    dim3 gg(D_ / 128, (M_TOT + 127) / 128);
    gemm_bias_tf32_kernel<<<gg, 256>>>(query, Wq, bq, q_p, M_TOT);
    gemm_bias_tf32_kernel<<<gg, 256>>>(key,   Wk, bk, k_p, M_TOT);
    gemm_bias_tf32_kernel<<<gg, 256>>>(value, Wv, bv, v_p, M_TOT);

    dim3 ga((N_ + 63) / 64, B_ * T_ * H_);
    attn_mma_kernel<<<ga, 128, ATTN_SMEM>>>(q_p, k_p, v_p, mask_p, attn_p);

    gemm_bias_tf32_kernel<<<gg, 256>>>(attn_p, Wo, bo, out, M_TOT);
}

// round 4
// speedup vs baseline: 4.5464x; 1.1125x over previous
#include <cuda_runtime.h>
#include <math.h>
#include <cstdint>

#define B_   8
#define T_   12
#define N_   307
#define D_   512
#define H_   8
#define HD_  64
#define M_TOT (B_*T_*N_)   // 29472
#define MP   320           // padded mask row pitch (floats, even -> float2 aligned)

// ---------------- device scratch (allocation-free rule) ----------------
__device__ float g_mask[N_*MP];
__device__ float g_q[M_TOT*D_];
__device__ float g_k[M_TOT*D_];
__device__ float g_v[M_TOT*D_];
__device__ float g_attn[M_TOT*D_];

__device__ __forceinline__ uint32_t f2tf32(float x) {
    uint32_t y;
    asm("cvt.rna.tf32.f32 %0, %1;" : "=r"(y) : "f"(x));
    return y;
}

// ---------------- mask = row-softmax(semantic_matrix), padded pitch ----
__global__ void mask_softmax_kernel(const float* __restrict__ sem,
                                    float* __restrict__ mask)
{
    int row = blockIdx.x;
    int tid = threadIdx.x;
    __shared__ float red[256];
    const float* x = sem + (size_t)row * N_;
    float v0 = (tid       < N_) ? x[tid]       : -INFINITY;
    float v1 = (tid + 256 < N_) ? x[tid + 256] : -INFINITY;
    red[tid] = fmaxf(v0, v1);
    __syncthreads();
    for (int s = 128; s > 0; s >>= 1) {
        if (tid < s) red[tid] = fmaxf(red[tid], red[tid + s]);
        __syncthreads();
    }
    float rowmax = red[0];
    __syncthreads();
    float e0 = (tid       < N_) ? __expf(v0 - rowmax) : 0.f;
    float e1 = (tid + 256 < N_) ? __expf(v1 - rowmax) : 0.f;
    red[tid] = e0 + e1;
    __syncthreads();
    for (int s = 128; s > 0; s >>= 1) {
        if (tid < s) red[tid] += red[tid + s];
        __syncthreads();
    }
    float inv = 1.f / red[0];
    if (tid       < N_) mask[(size_t)row * MP + tid]       = e0 * inv;
    if (tid + 256 < N_) mask[(size_t)row * MP + tid + 256] = e1 * inv;
    // pad tail so float2 loads never read garbage
    if (tid == 0) {
        for (int c = N_; c < MP; c++) mask[(size_t)row * MP + c] = 0.f;
    }
}

// ---------------- tf32 tensor-core GEMM, double-buffered ----------------
// tiles: 128x128x32, 256 threads = 8 warps (2m x 4n)
#define GEMM_SMEM ((2*128*36 + 2*32*136) * 4)   // 71680 B

__global__ __launch_bounds__(256)
void gemm_bias_tf32_kernel(const float* __restrict__ A, const float* __restrict__ W,
                           const float* __restrict__ bias, float* __restrict__ C,
                           int M)
{
    extern __shared__ float gsm[];
    float* As = gsm;                 // [2][128][36]
    float* Ws = gsm + 2 * 128 * 36;  // [2][32][136]

    int tid  = threadIdx.x;
    int lane = tid & 31;
    int wid  = tid >> 5;
    int warp_m = wid & 1;
    int warp_n = wid >> 1;
    int m0 = blockIdx.y * 128;
    int n0 = blockIdx.x * 128;

    float acc[4][4][4];
    #pragma unroll
    for (int mi = 0; mi < 4; mi++)
        #pragma unroll
        for (int ni = 0; ni < 4; ni++)
            #pragma unroll
            for (int r = 0; r < 4; r++) acc[mi][ni][r] = 0.f;

    float4 stA[4], stW[4];

    auto ldg_tile = [&](int k0) {
        #pragma unroll
        for (int r = 0; r < 4; r++) {
            int e  = tid + r * 256;
            int am = e >> 3;
            int ak = (e & 7) * 4;
            int gm = m0 + am;
            stA[r] = (gm < M) ? *(const float4*)(A + (size_t)gm * D_ + k0 + ak)
                              : make_float4(0.f, 0.f, 0.f, 0.f);
        }
        #pragma unroll
        for (int r = 0; r < 4; r++) {
            int e  = tid + r * 256;
            int wk = e >> 5;
            int wn = (e & 31) * 4;
            stW[r] = *(const float4*)(W + (size_t)(k0 + wk) * D_ + n0 + wn);
        }
    };
    auto sts_tile = [&](int b) {
        float* Ab = As + b * (128 * 36);
        float* Wb = Ws + b * (32 * 136);
        #pragma unroll
        for (int r = 0; r < 4; r++) {
            int e  = tid + r * 256;
            int am = e >> 3;
            int ak = (e & 7) * 4;
            uint4 v;
            v.x = f2tf32(stA[r].x); v.y = f2tf32(stA[r].y);
            v.z = f2tf32(stA[r].z); v.w = f2tf32(stA[r].w);
            *(uint4*)&Ab[am * 36 + ak] = v;
        }
        #pragma unroll
        for (int r = 0; r < 4; r++) {
            int e  = tid + r * 256;
            int wk = e >> 5;
            int wn = (e & 31) * 4;
            uint4 v;
            v.x = f2tf32(stW[r].x); v.y = f2tf32(stW[r].y);
            v.z = f2tf32(stW[r].z); v.w = f2tf32(stW[r].w);
            *(uint4*)&Wb[wk * 136 + wn] = v;
        }
    };

    ldg_tile(0);
    sts_tile(0);
    __syncthreads();

    int mrow_base = warp_m * 64 + (lane & 7) + ((lane >> 3) & 1) * 8;
    int kcol_sub  = (lane >> 4) * 4;
    int bk_row    = lane & 3;
    int bn_col    = warp_n * 32 + (lane >> 2);

    int buf = 0;
    for (int k0 = 0; k0 < D_; k0 += 32) {
        bool last = (k0 == D_ - 32);
        if (!last) ldg_tile(k0 + 32);

        float* Ab = As + buf * (128 * 36);
        float* Wb = Ws + buf * (32 * 136);
        #pragma unroll
        for (int kk = 0; kk < 4; kk++) {
            uint32_t a[4][4];
            #pragma unroll
            for (int mi = 0; mi < 4; mi++) {
                int m    = mrow_base + mi * 16;
                int kcol = kk * 8 + kcol_sub;
                uint32_t saddr = (uint32_t)__cvta_generic_to_shared(&Ab[m * 36 + kcol]);
                asm volatile(
                    "ldmatrix.sync.aligned.m8n8.x4.shared.b16 {%0,%1,%2,%3}, [%4];"
                    : "=r"(a[mi][0]), "=r"(a[mi][1]), "=r"(a[mi][2]), "=r"(a[mi][3])
                    : "r"(saddr));
            }
            #pragma unroll
            for (int ni = 0; ni < 4; ni++) {
                uint32_t b0 = __float_as_uint(Wb[(kk * 8 + bk_row    ) * 136 + bn_col + ni * 8]);
                uint32_t b1 = __float_as_uint(Wb[(kk * 8 + bk_row + 4) * 136 + bn_col + ni * 8]);
                #pragma unroll
                for (int mi = 0; mi < 4; mi++) {
                    asm volatile(
                        "mma.sync.aligned.m16n8k8.row.col.f32.tf32.tf32.f32 "
                        "{%0,%1,%2,%3}, {%4,%5,%6,%7}, {%8,%9}, {%0,%1,%2,%3};"
                        : "+f"(acc[mi][ni][0]), "+f"(acc[mi][ni][1]),
                          "+f"(acc[mi][ni][2]), "+f"(acc[mi][ni][3])
                        : "r"(a[mi][0]), "r"(a[mi][1]), "r"(a[mi][2]), "r"(a[mi][3]),
                          "r"(b0), "r"(b1));
                }
            }
        }
        if (!last) {
            sts_tile(buf ^ 1);
            __syncthreads();
            buf ^= 1;
        }
    }

    int crow = m0 + warp_m * 64 + (lane >> 2);
    int ccol0 = n0 + warp_n * 32 + 2 * (lane & 3);
    #pragma unroll
    for (int mi = 0; mi < 4; mi++) {
        int r0 = crow + mi * 16;
        #pragma unroll
        for (int ni = 0; ni < 4; ni++) {
            int cc = ccol0 + ni * 8;
            float b0 = bias[cc], b1 = bias[cc + 1];
            if (r0 < M) {
                float2 o = make_float2(acc[mi][ni][0] + b0, acc[mi][ni][1] + b1);
                *(float2*)(C + (size_t)r0 * D_ + cc) = o;
            }
            if (r0 + 8 < M) {
                float2 o = make_float2(acc[mi][ni][2] + b0, acc[mi][ni][3] + b1);
                *(float2*)(C + (size_t)(r0 + 8) * D_ + cc) = o;
            }
        }
    }
}

// ---------------- tf32 flash attention, single-pass exp ----------------
// block = 128 thr / 4 warps, q-tile 64 rows, warp = m16 x n64.
#define QP 68
#define KVP 72
#define ATTN_SMEM ((2*64*QP + 2*64*KVP) * 4)   // 71680 B

__global__ __launch_bounds__(128)
void attn_mma_kernel(const float* __restrict__ q, const float* __restrict__ k,
                     const float* __restrict__ v, const float* __restrict__ mask,
                     float* __restrict__ out)
{
    extern __shared__ float sm[];
    float* Qs = sm;                     // [64][QP]
    float* Ps = sm + 64 * QP;           // [64][QP]
    float* Ks = sm + 2 * 64 * QP;       // [64][KVP]
    float* Vs = Ks + 64 * KVP;          // [64][KVP]

    int tid  = threadIdx.x;
    int lane = tid & 31;
    int wid  = tid >> 5;
    int bth  = blockIdx.y;
    int bt   = bth / H_;
    int h    = bth % H_;
    int n0   = blockIdx.x * 64;
    size_t base = (size_t)bt * N_ * D_ + (size_t)h * HD_;

    // load Q tile [64][64] natural, tf32
    #pragma unroll
    for (int r = 0; r < 8; r++) {
        int e   = tid + r * 128;
        int row = e >> 4;
        int c4  = (e & 15) * 4;
        float4 val = make_float4(0.f, 0.f, 0.f, 0.f);
        int gn = n0 + row;
        if (gn < N_) val = *(const float4*)(q + base + (size_t)gn * D_ + c4);
        uint4 t;
        t.x = f2tf32(val.x); t.y = f2tf32(val.y);
        t.z = f2tf32(val.z); t.w = f2tf32(val.w);
        *(uint4*)&Qs[row * QP + c4] = t;
    }

    float oacc[8][4];
    #pragma unroll
    for (int ni = 0; ni < 8; ni++)
        #pragma unroll
        for (int r = 0; r < 4; r++) oacc[ni][r] = 0.f;
    float rs[2] = {0.f, 0.f};

    int qrow_frag = wid * 16 + (lane >> 2);
    int mrow_base = wid * 16 + (lane & 7) + ((lane >> 3) & 1) * 8;
    int kcol_sub  = (lane >> 4) * 4;
    int l2 = lane >> 2;
    int l4 = lane & 3;
    const float scale = 0.125f;

    for (int m0 = 0; m0 < 320; m0 += 64) {
        // K and V tiles, natural [kv][d], tf32 (V latency hidden behind QK)
        #pragma unroll
        for (int r = 0; r < 8; r++) {
            int e    = tid + r * 128;
            int mrow = e >> 4;
            int d4   = (e & 15) * 4;
            int gm = m0 + mrow;
            float4 kv = make_float4(0.f, 0.f, 0.f, 0.f);
            float4 vv = make_float4(0.f, 0.f, 0.f, 0.f);
            if (gm < N_) {
                kv = *(const float4*)(k + base + (size_t)gm * D_ + d4);
                vv = *(const float4*)(v + base + (size_t)gm * D_ + d4);
            }
            uint4 tk, tv;
            tk.x = f2tf32(kv.x); tk.y = f2tf32(kv.y);
            tk.z = f2tf32(kv.z); tk.w = f2tf32(kv.w);
            tv.x = f2tf32(vv.x); tv.y = f2tf32(vv.y);
            tv.z = f2tf32(vv.z); tv.w = f2tf32(vv.w);
            *(uint4*)&Ks[mrow * KVP + d4] = tk;
            *(uint4*)&Vs[mrow * KVP + d4] = tv;
        }
        __syncthreads();

        // ---- S = Q @ K^T ----
        float sacc[8][4];
        #pragma unroll
        for (int ni = 0; ni < 8; ni++)
            #pragma unroll
            for (int r = 0; r < 4; r++) sacc[ni][r] = 0.f;
        #pragma unroll
        for (int kk = 0; kk < 8; kk++) {
            uint32_t a[4];
            uint32_t saddr = (uint32_t)__cvta_generic_to_shared(
                &Qs[mrow_base * QP + kk * 8 + kcol_sub]);
            asm volatile(
                "ldmatrix.sync.aligned.m8n8.x4.shared.b16 {%0,%1,%2,%3}, [%4];"
                : "=r"(a[0]), "=r"(a[1]), "=r"(a[2]), "=r"(a[3])
                : "r"(saddr));
            #pragma unroll
            for (int ni = 0; ni < 8; ni++) {
                uint32_t b0 = __float_as_uint(Ks[(ni * 8 + l2) * KVP + kk * 8 + l4]);
                uint32_t b1 = __float_as_uint(Ks[(ni * 8 + l2) * KVP + kk * 8 + l4 + 4]);
                asm volatile(
                    "mma.sync.aligned.m16n8k8.row.col.f32.tf32.tf32.f32 "
                    "{%0,%1,%2,%3}, {%4,%5,%6,%7}, {%8,%9}, {%0,%1,%2,%3};"
                    : "+f"(sacc[ni][0]), "+f"(sacc[ni][1]),
                      "+f"(sacc[ni][2]), "+f"(sacc[ni][3])
                    : "r"(a[0]), "r"(a[1]), "r"(a[2]), "r"(a[3]),
                      "r"(b0), "r"(b1));
            }
        }

        // ---- single-pass: P = exp(S*scale*mask); rs += rowsum ----
        // |S*scale*mask| << 1 so exp never overflows; softmax is shift-invariant.
        #pragma unroll
        for (int u = 0; u < 2; u++) {
            int rloc = qrow_frag + u * 8;
            int gr   = n0 + rloc;
            const float* mrow = mask + (size_t)(gr < N_ ? gr : 0) * MP + m0;
            float local = 0.f;
            #pragma unroll
            for (int ni = 0; ni < 8; ni++) {
                int c = ni * 8 + 2 * l4;
                float2 mv = *(const float2*)(mrow + c);
                float e0 = 0.f, e1 = 0.f;
                if (m0 + c     < N_) e0 = __expf(sacc[ni][2 * u + 0] * scale * mv.x);
                if (m0 + c + 1 < N_) e1 = __expf(sacc[ni][2 * u + 1] * scale * mv.y);
                local += e0 + e1;
                Ps[rloc * QP + c]     = __uint_as_float(f2tf32(e0));
                Ps[rloc * QP + c + 1] = __uint_as_float(f2tf32(e1));
            }
            rs[u] += local;
        }
        __syncwarp();   // Ps rows are warp-band-private: warp-level ordering suffices

        // ---- O += P @ V ----
        #pragma unroll
        for (int kk = 0; kk < 8; kk++) {
            uint32_t a[4];
            uint32_t saddr = (uint32_t)__cvta_generic_to_shared(
                &Ps[mrow_base * QP + kk * 8 + kcol_sub]);
            asm volatile(
                "ldmatrix.sync.aligned.m8n8.x4.shared.b16 {%0,%1,%2,%3}, [%4];"
                : "=r"(a[0]), "=r"(a[1]), "=r"(a[2]), "=r"(a[3])
                : "r"(saddr));
            #pragma unroll
            for (int ni = 0; ni < 8; ni++) {
                uint32_t b0 = __float_as_uint(Vs[(kk * 8 + l4) * KVP + ni * 8 + l2]);
                uint32_t b1 = __float_as_uint(Vs[(kk * 8 + l4 + 4) * KVP + ni * 8 + l2]);
                asm volatile(
                    "mma.sync.aligned.m16n8k8.row.col.f32.tf32.tf32.f32 "
                    "{%0,%1,%2,%3}, {%4,%5,%6,%7}, {%8,%9}, {%0,%1,%2,%3};"
                    : "+f"(oacc[ni][0]), "+f"(oacc[ni][1]),
                      "+f"(oacc[ni][2]), "+f"(oacc[ni][3])
                    : "r"(a[0]), "r"(a[1]), "r"(a[2]), "r"(a[3]),
                      "r"(b0), "r"(b1));
            }
        }
        __syncthreads();   // all warps done reading Ks/Vs before next tile load
    }

    // epilogue: full row sums, normalize, store
    #pragma unroll
    for (int u = 0; u < 2; u++) {
        rs[u] += __shfl_xor_sync(0xffffffffu, rs[u], 1);
        rs[u] += __shfl_xor_sync(0xffffffffu, rs[u], 2);
        int gr = n0 + qrow_frag + u * 8;
        if (gr >= N_) continue;
        float inv = 1.f / rs[u];
        #pragma unroll
        for (int ni = 0; ni < 8; ni++) {
            int dc = ni * 8 + 2 * l4;
            float2 o = make_float2(oacc[ni][2 * u] * inv, oacc[ni][2 * u + 1] * inv);
            *(float2*)(out + base + (size_t)gr * D_ + dc) = o;
        }
    }
}

// ---------------- launch ----------------
extern "C" void kernel_launch(void* const* d_in, const int* in_sizes, int n_in,
                              void* d_out, int out_size)
{
    const float* query = (const float*)d_in[0];
    const float* key   = (const float*)d_in[1];
    const float* value = (const float*)d_in[2];
    const float* sem   = (const float*)d_in[3];
    const float* Wq    = (const float*)d_in[4];
    const float* bq    = (const float*)d_in[5];
    const float* Wk    = (const float*)d_in[6];
    const float* bk    = (const float*)d_in[7];
    const float* Wv    = (const float*)d_in[8];
    const float* bv    = (const float*)d_in[9];
    const float* Wo    = (const float*)d_in[10];
    const float* bo    = (const float*)d_in[11];
    float* out = (float*)d_out;

    float *mask_p, *q_p, *k_p, *v_p, *attn_p;
    cudaGetSymbolAddress((void**)&mask_p, g_mask);
    cudaGetSymbolAddress((void**)&q_p,    g_q);
    cudaGetSymbolAddress((void**)&k_p,    g_k);
    cudaGetSymbolAddress((void**)&v_p,    g_v);
    cudaGetSymbolAddress((void**)&attn_p, g_attn);

    static bool attr_set = false;
    if (!attr_set) {
        cudaFuncSetAttribute(attn_mma_kernel,
                             cudaFuncAttributeMaxDynamicSharedMemorySize, ATTN_SMEM);
        cudaFuncSetAttribute(gemm_bias_tf32_kernel,
                             cudaFuncAttributeMaxDynamicSharedMemorySize, GEMM_SMEM);
        attr_set = true;
    }

    mask_softmax_kernel<<<N_, 256>>>(sem, mask_p);

    dim3 gg(D_ / 128, (M_TOT + 127) / 128);
    gemm_bias_tf32_kernel<<<gg, 256, GEMM_SMEM>>>(query, Wq, bq, q_p, M_TOT);
    gemm_bias_tf32_kernel<<<gg, 256, GEMM_SMEM>>>(key,   Wk, bk, k_p, M_TOT);
    gemm_bias_tf32_kernel<<<gg, 256, GEMM_SMEM>>>(value, Wv, bv, v_p, M_TOT);

    dim3 ga((N_ + 63) / 64, B_ * T_ * H_);
    attn_mma_kernel<<<ga, 128, ATTN_SMEM>>>(q_p, k_p, v_p, mask_p, attn_p);

    gemm_bias_tf32_kernel<<<gg, 256, GEMM_SMEM>>>(attn_p, Wo, bo, out, M_TOT);
}

// round 6
// speedup vs baseline: 5.2088x; 1.1457x over previous
#include <cuda_runtime.h>
#include <math.h>
#include <cstdint>

#define B_   8
#define T_   12
#define N_   307
#define D_   512
#define H_   8
#define HD_  64
#define M_TOT (B_*T_*N_)   // 29472
#define MP   320           // padded mask row pitch

// ---------------- device scratch (allocation-free rule) ----------------
__device__ float g_mask[N_*MP];
__device__ float g_q[M_TOT*D_];
__device__ float g_k[M_TOT*D_];
__device__ float g_v[M_TOT*D_];
__device__ float g_attn[M_TOT*D_];
__device__ float g_wt[4*D_*D_];     // transposed + tf32-rounded weights [N][K]

__device__ __forceinline__ uint32_t f2tf32(float x) {
    uint32_t y;
    asm("cvt.rna.tf32.f32 %0, %1;" : "=r"(y) : "f"(x));
    return y;
}

// ---------------- mask = row-softmax(semantic_matrix), padded pitch ----
__global__ void mask_softmax_kernel(const float* __restrict__ sem,
                                    float* __restrict__ mask)
{
    int row = blockIdx.x;
    int tid = threadIdx.x;
    __shared__ float red[256];
    const float* x = sem + (size_t)row * N_;
    float v0 = (tid       < N_) ? x[tid]       : -INFINITY;
    float v1 = (tid + 256 < N_) ? x[tid + 256] : -INFINITY;
    red[tid] = fmaxf(v0, v1);
    __syncthreads();
    for (int s = 128; s > 0; s >>= 1) {
        if (tid < s) red[tid] = fmaxf(red[tid], red[tid + s]);
        __syncthreads();
    }
    float rowmax = red[0];
    __syncthreads();
    float e0 = (tid       < N_) ? __expf(v0 - rowmax) : 0.f;
    float e1 = (tid + 256 < N_) ? __expf(v1 - rowmax) : 0.f;
    red[tid] = e0 + e1;
    __syncthreads();
    for (int s = 128; s > 0; s >>= 1) {
        if (tid < s) red[tid] += red[tid + s];
        __syncthreads();
    }
    float inv = 1.f / red[0];
    if (tid       < N_) mask[(size_t)row * MP + tid]       = e0 * inv;
    if (tid + 256 < N_) mask[(size_t)row * MP + tid + 256] = e1 * inv;
    if (tid == 0)
        for (int c = N_; c < MP; c++) mask[(size_t)row * MP + c] = 0.f;
}

// ---------------- W -> W^T (tf32-rounded), 4 matrices ----------------
__global__ void transpose_w_kernel(const float* __restrict__ w0,
                                   const float* __restrict__ w1,
                                   const float* __restrict__ w2,
                                   const float* __restrict__ w3,
                                   float* __restrict__ wt)
{
    __shared__ float t[32][33];
    int z  = blockIdx.z;
    const float* src = (z == 0) ? w0 : (z == 1) ? w1 : (z == 2) ? w2 : w3;
    float* dst = wt + (size_t)z * D_ * D_;
    int tx = threadIdx.x, ty = threadIdx.y;
    int bx = blockIdx.x * 32, by = blockIdx.y * 32;
    #pragma unroll
    for (int i = 0; i < 32; i += 8)
        t[ty + i][tx] = src[(size_t)(by + ty + i) * D_ + bx + tx];
    __syncthreads();
    #pragma unroll
    for (int i = 0; i < 32; i += 8)
        dst[(size_t)(bx + ty + i) * D_ + by + tx] =
            __uint_as_float(f2tf32(t[tx][ty + i]));
}

// ---------------- tf32 mma.sync GEMM, B via ldmatrix, cp.async W -------
// tiles: 128x128x32, 256 thr = 8 warps (2m x 4n). A smem [m][36], W smem [n][36].
#define TILE_F  (128 * 36)
#define GEMM_SMEM (4 * TILE_F * 4)   // 2 bufs x (A + W) = 73728 B

__global__ __launch_bounds__(256, 2)
void gemm_bias_tf32_kernel(const float* __restrict__ A0, const float* __restrict__ A1,
                           const float* __restrict__ A2, const float* __restrict__ WtB,
                           const float* __restrict__ b0p, const float* __restrict__ b1p,
                           const float* __restrict__ b2p,
                           float* __restrict__ C0, float* __restrict__ C1,
                           float* __restrict__ C2, int M)
{
    extern __shared__ float gsm[];
    // layout: buf0 A, buf0 W, buf1 A, buf1 W
    int z = blockIdx.z;
    const float* A    = (z == 0) ? A0 : (z == 1) ? A1 : A2;
    const float* Wt   = WtB + (size_t)z * D_ * D_;
    const float* bias = (z == 0) ? b0p : (z == 1) ? b1p : b2p;
    float* C          = (z == 0) ? C0 : (z == 1) ? C1 : C2;

    int tid  = threadIdx.x;
    int lane = tid & 31;
    int wid  = tid >> 5;
    int warp_m = wid & 1;
    int warp_n = wid >> 1;
    int m0 = blockIdx.y * 128;
    int n0 = blockIdx.x * 128;

    float acc[4][4][4];
    #pragma unroll
    for (int mi = 0; mi < 4; mi++)
        #pragma unroll
        for (int ni = 0; ni < 4; ni++)
            #pragma unroll
            for (int r = 0; r < 4; r++) acc[mi][ni][r] = 0.f;

    float4 stA[4];

    // per-thread A tile coords
    auto ldg_A = [&](int k0) {
        #pragma unroll
        for (int r = 0; r < 4; r++) {
            int e  = tid + r * 256;
            int am = e >> 3;
            int ak = (e & 7) * 4;
            int gm = m0 + am;
            stA[r] = (gm < M) ? *(const float4*)(A + (size_t)gm * D_ + k0 + ak)
                              : make_float4(0.f, 0.f, 0.f, 0.f);
        }
    };
    auto sts_A = [&](int b) {
        float* Ab = gsm + b * 2 * TILE_F;
        #pragma unroll
        for (int r = 0; r < 4; r++) {
            int e  = tid + r * 256;
            int am = e >> 3;
            int ak = (e & 7) * 4;
            uint4 v;
            v.x = f2tf32(stA[r].x); v.y = f2tf32(stA[r].y);
            v.z = f2tf32(stA[r].z); v.w = f2tf32(stA[r].w);
            *(uint4*)&Ab[am * 36 + ak] = v;
        }
    };
    // cp.async W tile (pre-rounded) into buffer b
    auto cpa_W = [&](int b, int k0) {
        float* Wb = gsm + b * 2 * TILE_F + TILE_F;
        #pragma unroll
        for (int r = 0; r < 4; r++) {
            int e   = tid + r * 256;
            int row = e >> 3;
            int c4  = (e & 7) * 4;
            uint32_t dst = (uint32_t)__cvta_generic_to_shared(&Wb[row * 36 + c4]);
            const float* src = Wt + (size_t)(n0 + row) * D_ + k0 + c4;
            asm volatile("cp.async.ca.shared.global [%0], [%1], 16;"
                         :: "r"(dst), "l"(src));
        }
        asm volatile("cp.async.commit_group;");
    };

    ldg_A(0);
    cpa_W(0, 0);
    sts_A(0);
    asm volatile("cp.async.wait_group 0;");
    __syncthreads();

    int mrow_base = warp_m * 64 + (lane & 7) + ((lane >> 3) & 1) * 8;
    int kcol_sub  = (lane >> 4) * 4;
    // B ldmatrix lane coords (within warp's 32-wide n band)
    int bn_row = warp_n * 32 + ((lane >> 4) & 1) * 8 + (lane & 7);
    int bk_sub = ((lane >> 3) & 1) * 4;

    int buf = 0;
    for (int k0 = 0; k0 < D_; k0 += 32) {
        bool last = (k0 == D_ - 32);
        if (!last) {
            ldg_A(k0 + 32);
            cpa_W(buf ^ 1, k0 + 32);
        }

        float* Ab = gsm + buf * 2 * TILE_F;
        float* Wb = Ab + TILE_F;
        #pragma unroll
        for (int kk = 0; kk < 4; kk++) {
            uint32_t a[4][4];
            #pragma unroll
            for (int mi = 0; mi < 4; mi++) {
                uint32_t saddr = (uint32_t)__cvta_generic_to_shared(
                    &Ab[(mrow_base + mi * 16) * 36 + kk * 8 + kcol_sub]);
                asm volatile(
                    "ldmatrix.sync.aligned.m8n8.x4.shared.b16 {%0,%1,%2,%3}, [%4];"
                    : "=r"(a[mi][0]), "=r"(a[mi][1]), "=r"(a[mi][2]), "=r"(a[mi][3])
                    : "r"(saddr));
            }
            uint32_t bfr[2][4];
            #pragma unroll
            for (int t = 0; t < 2; t++) {
                uint32_t saddr = (uint32_t)__cvta_generic_to_shared(
                    &Wb[(bn_row + t * 16) * 36 + kk * 8 + bk_sub]);
                asm volatile(
                    "ldmatrix.sync.aligned.m8n8.x4.shared.b16 {%0,%1,%2,%3}, [%4];"
                    : "=r"(bfr[t][0]), "=r"(bfr[t][1]), "=r"(bfr[t][2]), "=r"(bfr[t][3])
                    : "r"(saddr));
            }
            #pragma unroll
            for (int ni = 0; ni < 4; ni++) {
                uint32_t b0 = bfr[ni >> 1][(ni & 1) * 2];
                uint32_t b1 = bfr[ni >> 1][(ni & 1) * 2 + 1];
                #pragma unroll
                for (int mi = 0; mi < 4; mi++) {
                    asm volatile(
                        "mma.sync.aligned.m16n8k8.row.col.f32.tf32.tf32.f32 "
                        "{%0,%1,%2,%3}, {%4,%5,%6,%7}, {%8,%9}, {%0,%1,%2,%3};"
                        : "+f"(acc[mi][ni][0]), "+f"(acc[mi][ni][1]),
                          "+f"(acc[mi][ni][2]), "+f"(acc[mi][ni][3])
                        : "r"(a[mi][0]), "r"(a[mi][1]), "r"(a[mi][2]), "r"(a[mi][3]),
                          "r"(b0), "r"(b1));
                }
            }
        }
        if (!last) {
            sts_A(buf ^ 1);
            asm volatile("cp.async.wait_group 0;");
            __syncthreads();
            buf ^= 1;
        }
    }

    int crow = m0 + warp_m * 64 + (lane >> 2);
    int ccol0 = n0 + warp_n * 32 + 2 * (lane & 3);
    #pragma unroll
    for (int mi = 0; mi < 4; mi++) {
        int r0 = crow + mi * 16;
        #pragma unroll
        for (int ni = 0; ni < 4; ni++) {
            int cc = ccol0 + ni * 8;
            float bb0 = bias[cc], bb1 = bias[cc + 1];
            if (r0 < M) {
                float2 o = make_float2(acc[mi][ni][0] + bb0, acc[mi][ni][1] + bb1);
                *(float2*)(C + (size_t)r0 * D_ + cc) = o;
            }
            if (r0 + 8 < M) {
                float2 o = make_float2(acc[mi][ni][2] + bb0, acc[mi][ni][3] + bb1);
                *(float2*)(C + (size_t)(r0 + 8) * D_ + cc) = o;
            }
        }
    }
}

// ---------------- tf32 flash attention, single-pass exp (unchanged) ----
#define QP 68
#define KVP 72
#define ATTN_SMEM ((2*64*QP + 2*64*KVP) * 4)   // 71680 B

__global__ __launch_bounds__(128)
void attn_mma_kernel(const float* __restrict__ q, const float* __restrict__ k,
                     const float* __restrict__ v, const float* __restrict__ mask,
                     float* __restrict__ out)
{
    extern __shared__ float sm[];
    float* Qs = sm;                     // [64][QP]
    float* Ps = sm + 64 * QP;           // [64][QP]
    float* Ks = sm + 2 * 64 * QP;       // [64][KVP]
    float* Vs = Ks + 64 * KVP;          // [64][KVP]

    int tid  = threadIdx.x;
    int lane = tid & 31;
    int wid  = tid >> 5;
    int bth  = blockIdx.y;
    int bt   = bth / H_;
    int h    = bth % H_;
    int n0   = blockIdx.x * 64;
    size_t base = (size_t)bt * N_ * D_ + (size_t)h * HD_;

    #pragma unroll
    for (int r = 0; r < 8; r++) {
        int e   = tid + r * 128;
        int row = e >> 4;
        int c4  = (e & 15) * 4;
        float4 val = make_float4(0.f, 0.f, 0.f, 0.f);
        int gn = n0 + row;
        if (gn < N_) val = *(const float4*)(q + base + (size_t)gn * D_ + c4);
        uint4 t;
        t.x = f2tf32(val.x); t.y = f2tf32(val.y);
        t.z = f2tf32(val.z); t.w = f2tf32(val.w);
        *(uint4*)&Qs[row * QP + c4] = t;
    }

    float oacc[8][4];
    #pragma unroll
    for (int ni = 0; ni < 8; ni++)
        #pragma unroll
        for (int r = 0; r < 4; r++) oacc[ni][r] = 0.f;
    float rs[2] = {0.f, 0.f};

    int qrow_frag = wid * 16 + (lane >> 2);
    int mrow_base = wid * 16 + (lane & 7) + ((lane >> 3) & 1) * 8;
    int kcol_sub  = (lane >> 4) * 4;
    int l2 = lane >> 2;
    int l4 = lane & 3;
    const float scale = 0.125f;

    for (int m0 = 0; m0 < 320; m0 += 64) {
        #pragma unroll
        for (int r = 0; r < 8; r++) {
            int e    = tid + r * 128;
            int mrow = e >> 4;
            int d4   = (e & 15) * 4;
            int gm = m0 + mrow;
            float4 kv = make_float4(0.f, 0.f, 0.f, 0.f);
            float4 vv = make_float4(0.f, 0.f, 0.f, 0.f);
            if (gm < N_) {
                kv = *(const float4*)(k + base + (size_t)gm * D_ + d4);
                vv = *(const float4*)(v + base + (size_t)gm * D_ + d4);
            }
            uint4 tk, tv;
            tk.x = f2tf32(kv.x); tk.y = f2tf32(kv.y);
            tk.z = f2tf32(kv.z); tk.w = f2tf32(kv.w);
            tv.x = f2tf32(vv.x); tv.y = f2tf32(vv.y);
            tv.z = f2tf32(vv.z); tv.w = f2tf32(vv.w);
            *(uint4*)&Ks[mrow * KVP + d4] = tk;
            *(uint4*)&Vs[mrow * KVP + d4] = tv;
        }
        __syncthreads();

        float sacc[8][4];
        #pragma unroll
        for (int ni = 0; ni < 8; ni++)
            #pragma unroll
            for (int r = 0; r < 4; r++) sacc[ni][r] = 0.f;
        #pragma unroll
        for (int kk = 0; kk < 8; kk++) {
            uint32_t a[4];
            uint32_t saddr = (uint32_t)__cvta_generic_to_shared(
                &Qs[mrow_base * QP + kk * 8 + kcol_sub]);
            asm volatile(
                "ldmatrix.sync.aligned.m8n8.x4.shared.b16 {%0,%1,%2,%3}, [%4];"
                : "=r"(a[0]), "=r"(a[1]), "=r"(a[2]), "=r"(a[3])
                : "r"(saddr));
            #pragma unroll
            for (int ni = 0; ni < 8; ni++) {
                uint32_t b0 = __float_as_uint(Ks[(ni * 8 + l2) * KVP + kk * 8 + l4]);
                uint32_t b1 = __float_as_uint(Ks[(ni * 8 + l2) * KVP + kk * 8 + l4 + 4]);
                asm volatile(
                    "mma.sync.aligned.m16n8k8.row.col.f32.tf32.tf32.f32 "
                    "{%0,%1,%2,%3}, {%4,%5,%6,%7}, {%8,%9}, {%0,%1,%2,%3};"
                    : "+f"(sacc[ni][0]), "+f"(sacc[ni][1]),
                      "+f"(sacc[ni][2]), "+f"(sacc[ni][3])
                    : "r"(a[0]), "r"(a[1]), "r"(a[2]), "r"(a[3]),
                      "r"(b0), "r"(b1));
            }
        }

        #pragma unroll
        for (int u = 0; u < 2; u++) {
            int rloc = qrow_frag + u * 8;
            int gr   = n0 + rloc;
            const float* mrow = mask + (size_t)(gr < N_ ? gr : 0) * MP + m0;
            float local = 0.f;
            #pragma unroll
            for (int ni = 0; ni < 8; ni++) {
                int c = ni * 8 + 2 * l4;
                float2 mv = *(const float2*)(mrow + c);
                float e0 = 0.f, e1 = 0.f;
                if (m0 + c     < N_) e0 = __expf(sacc[ni][2 * u + 0] * scale * mv.x);
                if (m0 + c + 1 < N_) e1 = __expf(sacc[ni][2 * u + 1] * scale * mv.y);
                local += e0 + e1;
                Ps[rloc * QP + c]     = __uint_as_float(f2tf32(e0));
                Ps[rloc * QP + c + 1] = __uint_as_float(f2tf32(e1));
            }
            rs[u] += local;
        }
        __syncwarp();

        #pragma unroll
        for (int kk = 0; kk < 8; kk++) {
            uint32_t a[4];
            uint32_t saddr = (uint32_t)__cvta_generic_to_shared(
                &Ps[mrow_base * QP + kk * 8 + kcol_sub]);
            asm volatile(
                "ldmatrix.sync.aligned.m8n8.x4.shared.b16 {%0,%1,%2,%3}, [%4];"
                : "=r"(a[0]), "=r"(a[1]), "=r"(a[2]), "=r"(a[3])
                : "r"(saddr));
            #pragma unroll
            for (int ni = 0; ni < 8; ni++) {
                uint32_t b0 = __float_as_uint(Vs[(kk * 8 + l4) * KVP + ni * 8 + l2]);
                uint32_t b1 = __float_as_uint(Vs[(kk * 8 + l4 + 4) * KVP + ni * 8 + l2]);
                asm volatile(
                    "mma.sync.aligned.m16n8k8.row.col.f32.tf32.tf32.f32 "
                    "{%0,%1,%2,%3}, {%4,%5,%6,%7}, {%8,%9}, {%0,%1,%2,%3};"
                    : "+f"(oacc[ni][0]), "+f"(oacc[ni][1]),
                      "+f"(oacc[ni][2]), "+f"(oacc[ni][3])
                    : "r"(a[0]), "r"(a[1]), "r"(a[2]), "r"(a[3]),
                      "r"(b0), "r"(b1));
            }
        }
        __syncthreads();
    }

    #pragma unroll
    for (int u = 0; u < 2; u++) {
        rs[u] += __shfl_xor_sync(0xffffffffu, rs[u], 1);
        rs[u] += __shfl_xor_sync(0xffffffffu, rs[u], 2);
        int gr = n0 + qrow_frag + u * 8;
        if (gr >= N_) continue;
        float inv = 1.f / rs[u];
        #pragma unroll
        for (int ni = 0; ni < 8; ni++) {
            int dc = ni * 8 + 2 * l4;
            float2 o = make_float2(oacc[ni][2 * u] * inv, oacc[ni][2 * u + 1] * inv);
            *(float2*)(out + base + (size_t)gr * D_ + dc) = o;
        }
    }
}

// ---------------- launch ----------------
extern "C" void kernel_launch(void* const* d_in, const int* in_sizes, int n_in,
                              void* d_out, int out_size)
{
    const float* query = (const float*)d_in[0];
    const float* key   = (const float*)d_in[1];
    const float* value = (const float*)d_in[2];
    const float* sem   = (const float*)d_in[3];
    const float* Wq    = (const float*)d_in[4];
    const float* bq    = (const float*)d_in[5];
    const float* Wk    = (const float*)d_in[6];
    const float* bk    = (const float*)d_in[7];
    const float* Wv    = (const float*)d_in[8];
    const float* bv    = (const float*)d_in[9];
    const float* Wo    = (const float*)d_in[10];
    const float* bo    = (const float*)d_in[11];
    float* out = (float*)d_out;

    float *mask_p, *q_p, *k_p, *v_p, *attn_p, *wt_p;
    cudaGetSymbolAddress((void**)&mask_p, g_mask);
    cudaGetSymbolAddress((void**)&q_p,    g_q);
    cudaGetSymbolAddress((void**)&k_p,    g_k);
    cudaGetSymbolAddress((void**)&v_p,    g_v);
    cudaGetSymbolAddress((void**)&attn_p, g_attn);
    cudaGetSymbolAddress((void**)&wt_p,   g_wt);

    static bool attr_set = false;
    if (!attr_set) {
        cudaFuncSetAttribute(attn_mma_kernel,
                             cudaFuncAttributeMaxDynamicSharedMemorySize, ATTN_SMEM);
        cudaFuncSetAttribute(gemm_bias_tf32_kernel,
                             cudaFuncAttributeMaxDynamicSharedMemorySize, GEMM_SMEM);
        attr_set = true;
    }

    mask_softmax_kernel<<<N_, 256>>>(sem, mask_p);

    dim3 tg(D_ / 32, D_ / 32, 4);
    transpose_w_kernel<<<tg, dim3(32, 8)>>>(Wq, Wk, Wv, Wo, wt_p);

    // fused Q/K/V projections (grid.z = 3)
    dim3 g3(D_ / 128, (M_TOT + 127) / 128, 3);
    gemm_bias_tf32_kernel<<<g3, 256, GEMM_SMEM>>>(
        query, key, value, wt_p, bq, bk, bv, q_p, k_p, v_p, M_TOT);

    dim3 ga((N_ + 63) / 64, B_ * T_ * H_);
    attn_mma_kernel<<<ga, 128, ATTN_SMEM>>>(q_p, k_p, v_p, mask_p, attn_p);

    // output projection (grid.z = 1, Wt slot 3)
    dim3 g1(D_ / 128, (M_TOT + 127) / 128, 1);
    gemm_bias_tf32_kernel<<<g1, 256, GEMM_SMEM>>>(
        attn_p, attn_p, attn_p, wt_p + 3 * (size_t)D_ * D_, bo, bo, bo,
        out, out, out, M_TOT);
}

// round 7
// speedup vs baseline: 5.2912x; 1.0158x over previous
#include <cuda_runtime.h>
#include <math.h>
#include <cstdint>

#define B_   8
#define T_   12
#define N_   307
#define D_   512
#define H_   8
#define HD_  64
#define M_TOT (B_*T_*N_)   // 29472
#define MP   320           // padded mask row pitch

// ---------------- device scratch (allocation-free rule) ----------------
__device__ float g_mask[N_*MP];
__device__ float g_q[M_TOT*D_];
__device__ float g_k[M_TOT*D_];
__device__ float g_v[M_TOT*D_];
__device__ float g_attn[M_TOT*D_];
__device__ float g_wt[4*D_*D_];     // transposed + tf32-rounded weights [N][K]

__device__ __forceinline__ uint32_t f2tf32(float x) {
    uint32_t y;
    asm("cvt.rna.tf32.f32 %0, %1;" : "=r"(y) : "f"(x));
    return y;
}

// ---------------- mask = row-softmax(semantic_matrix), padded pitch ----
__global__ void mask_softmax_kernel(const float* __restrict__ sem,
                                    float* __restrict__ mask)
{
    int row = blockIdx.x;
    int tid = threadIdx.x;
    __shared__ float red[256];
    const float* x = sem + (size_t)row * N_;
    float v0 = (tid       < N_) ? x[tid]       : -INFINITY;
    float v1 = (tid + 256 < N_) ? x[tid + 256] : -INFINITY;
    red[tid] = fmaxf(v0, v1);
    __syncthreads();
    for (int s = 128; s > 0; s >>= 1) {
        if (tid < s) red[tid] = fmaxf(red[tid], red[tid + s]);
        __syncthreads();
    }
    float rowmax = red[0];
    __syncthreads();
    float e0 = (tid       < N_) ? __expf(v0 - rowmax) : 0.f;
    float e1 = (tid + 256 < N_) ? __expf(v1 - rowmax) : 0.f;
    red[tid] = e0 + e1;
    __syncthreads();
    for (int s = 128; s > 0; s >>= 1) {
        if (tid < s) red[tid] += red[tid + s];
        __syncthreads();
    }
    float inv = 1.f / red[0];
    if (tid       < N_) mask[(size_t)row * MP + tid]       = e0 * inv;
    if (tid + 256 < N_) mask[(size_t)row * MP + tid + 256] = e1 * inv;
    if (tid == 0)
        for (int c = N_; c < MP; c++) mask[(size_t)row * MP + c] = 0.f;
}

// ---------------- W -> W^T (tf32-rounded), 4 matrices ----------------
__global__ void transpose_w_kernel(const float* __restrict__ w0,
                                   const float* __restrict__ w1,
                                   const float* __restrict__ w2,
                                   const float* __restrict__ w3,
                                   float* __restrict__ wt)
{
    __shared__ float t[32][33];
    int z  = blockIdx.z;
    const float* src = (z == 0) ? w0 : (z == 1) ? w1 : (z == 2) ? w2 : w3;
    float* dst = wt + (size_t)z * D_ * D_;
    int tx = threadIdx.x, ty = threadIdx.y;
    int bx = blockIdx.x * 32, by = blockIdx.y * 32;
    #pragma unroll
    for (int i = 0; i < 32; i += 8)
        t[ty + i][tx] = src[(size_t)(by + ty + i) * D_ + bx + tx];
    __syncthreads();
    #pragma unroll
    for (int i = 0; i < 32; i += 8)
        dst[(size_t)(bx + ty + i) * D_ + by + tx] =
            __uint_as_float(f2tf32(t[tx][ty + i]));
}

// ---------------- tf32 mma.sync GEMM, B via ldmatrix, cp.async W -------
#define TILE_F  (128 * 36)
#define GEMM_SMEM (4 * TILE_F * 4)   // 73728 B

__global__ __launch_bounds__(256, 2)
void gemm_bias_tf32_kernel(const float* __restrict__ A0, const float* __restrict__ A1,
                           const float* __restrict__ A2, const float* __restrict__ WtB,
                           const float* __restrict__ b0p, const float* __restrict__ b1p,
                           const float* __restrict__ b2p,
                           float* __restrict__ C0, float* __restrict__ C1,
                           float* __restrict__ C2, int M)
{
    extern __shared__ float gsm[];
    int z = blockIdx.z;
    const float* A    = (z == 0) ? A0 : (z == 1) ? A1 : A2;
    const float* Wt   = WtB + (size_t)z * D_ * D_;
    const float* bias = (z == 0) ? b0p : (z == 1) ? b1p : b2p;
    float* C          = (z == 0) ? C0 : (z == 1) ? C1 : C2;

    int tid  = threadIdx.x;
    int lane = tid & 31;
    int wid  = tid >> 5;
    int warp_m = wid & 1;
    int warp_n = wid >> 1;
    int m0 = blockIdx.y * 128;
    int n0 = blockIdx.x * 128;

    float acc[4][4][4];
    #pragma unroll
    for (int mi = 0; mi < 4; mi++)
        #pragma unroll
        for (int ni = 0; ni < 4; ni++)
            #pragma unroll
            for (int r = 0; r < 4; r++) acc[mi][ni][r] = 0.f;

    float4 stA[4];

    auto ldg_A = [&](int k0) {
        #pragma unroll
        for (int r = 0; r < 4; r++) {
            int e  = tid + r * 256;
            int am = e >> 3;
            int ak = (e & 7) * 4;
            int gm = m0 + am;
            stA[r] = (gm < M) ? *(const float4*)(A + (size_t)gm * D_ + k0 + ak)
                              : make_float4(0.f, 0.f, 0.f, 0.f);
        }
    };
    auto sts_A = [&](int b) {
        float* Ab = gsm + b * 2 * TILE_F;
        #pragma unroll
        for (int r = 0; r < 4; r++) {
            int e  = tid + r * 256;
            int am = e >> 3;
            int ak = (e & 7) * 4;
            uint4 v;
            v.x = f2tf32(stA[r].x); v.y = f2tf32(stA[r].y);
            v.z = f2tf32(stA[r].z); v.w = f2tf32(stA[r].w);
            *(uint4*)&Ab[am * 36 + ak] = v;
        }
    };
    auto cpa_W = [&](int b, int k0) {
        float* Wb = gsm + b * 2 * TILE_F + TILE_F;
        #pragma unroll
        for (int r = 0; r < 4; r++) {
            int e   = tid + r * 256;
            int row = e >> 3;
            int c4  = (e & 7) * 4;
            uint32_t dst = (uint32_t)__cvta_generic_to_shared(&Wb[row * 36 + c4]);
            const float* src = Wt + (size_t)(n0 + row) * D_ + k0 + c4;
            asm volatile("cp.async.ca.shared.global [%0], [%1], 16;"
                         :: "r"(dst), "l"(src));
        }
        asm volatile("cp.async.commit_group;");
    };

    ldg_A(0);
    cpa_W(0, 0);
    sts_A(0);
    asm volatile("cp.async.wait_group 0;");
    __syncthreads();

    int mrow_base = warp_m * 64 + (lane & 7) + ((lane >> 3) & 1) * 8;
    int kcol_sub  = (lane >> 4) * 4;
    int bn_row = warp_n * 32 + ((lane >> 4) & 1) * 8 + (lane & 7);
    int bk_sub = ((lane >> 3) & 1) * 4;

    int buf = 0;
    for (int k0 = 0; k0 < D_; k0 += 32) {
        bool last = (k0 == D_ - 32);
        if (!last) {
            ldg_A(k0 + 32);
            cpa_W(buf ^ 1, k0 + 32);
        }

        float* Ab = gsm + buf * 2 * TILE_F;
        float* Wb = Ab + TILE_F;
        #pragma unroll
        for (int kk = 0; kk < 4; kk++) {
            uint32_t a[4][4];
            #pragma unroll
            for (int mi = 0; mi < 4; mi++) {
                uint32_t saddr = (uint32_t)__cvta_generic_to_shared(
                    &Ab[(mrow_base + mi * 16) * 36 + kk * 8 + kcol_sub]);
                asm volatile(
                    "ldmatrix.sync.aligned.m8n8.x4.shared.b16 {%0,%1,%2,%3}, [%4];"
                    : "=r"(a[mi][0]), "=r"(a[mi][1]), "=r"(a[mi][2]), "=r"(a[mi][3])
                    : "r"(saddr));
            }
            uint32_t bfr[2][4];
            #pragma unroll
            for (int t = 0; t < 2; t++) {
                uint32_t saddr = (uint32_t)__cvta_generic_to_shared(
                    &Wb[(bn_row + t * 16) * 36 + kk * 8 + bk_sub]);
                asm volatile(
                    "ldmatrix.sync.aligned.m8n8.x4.shared.b16 {%0,%1,%2,%3}, [%4];"
                    : "=r"(bfr[t][0]), "=r"(bfr[t][1]), "=r"(bfr[t][2]), "=r"(bfr[t][3])
                    : "r"(saddr));
            }
            #pragma unroll
            for (int ni = 0; ni < 4; ni++) {
                uint32_t b0 = bfr[ni >> 1][(ni & 1) * 2];
                uint32_t b1 = bfr[ni >> 1][(ni & 1) * 2 + 1];
                #pragma unroll
                for (int mi = 0; mi < 4; mi++) {
                    asm volatile(
                        "mma.sync.aligned.m16n8k8.row.col.f32.tf32.tf32.f32 "
                        "{%0,%1,%2,%3}, {%4,%5,%6,%7}, {%8,%9}, {%0,%1,%2,%3};"
                        : "+f"(acc[mi][ni][0]), "+f"(acc[mi][ni][1]),
                          "+f"(acc[mi][ni][2]), "+f"(acc[mi][ni][3])
                        : "r"(a[mi][0]), "r"(a[mi][1]), "r"(a[mi][2]), "r"(a[mi][3]),
                          "r"(b0), "r"(b1));
                }
            }
        }
        if (!last) {
            sts_A(buf ^ 1);
            asm volatile("cp.async.wait_group 0;");
            __syncthreads();
            buf ^= 1;
        }
    }

    int crow = m0 + warp_m * 64 + (lane >> 2);
    int ccol0 = n0 + warp_n * 32 + 2 * (lane & 3);
    #pragma unroll
    for (int mi = 0; mi < 4; mi++) {
        int r0 = crow + mi * 16;
        #pragma unroll
        for (int ni = 0; ni < 4; ni++) {
            int cc = ccol0 + ni * 8;
            float bb0 = bias[cc], bb1 = bias[cc + 1];
            if (r0 < M) {
                float2 o = make_float2(acc[mi][ni][0] + bb0, acc[mi][ni][1] + bb1);
                *(float2*)(C + (size_t)r0 * D_ + cc) = o;
            }
            if (r0 + 8 < M) {
                float2 o = make_float2(acc[mi][ni][2] + bb0, acc[mi][ni][3] + bb1);
                *(float2*)(C + (size_t)(r0 + 8) * D_ + cc) = o;
            }
        }
    }
}

// ---------------- tf32 flash attention v2 ----------------
// 256 thr / 8 warps, q-tile 128 rows, warp w = rows w*16..+15 (m16 x n64).
// Qs/Ps pitch 68 (ldmatrix-friendly odd*16B), Ks pitch 68 (ldmatrix B),
// Vs pitch 72 (scalar B, conflict-free).
#define QP2 68
#define VP2 72
#define ATTN_SMEM ((2*128*QP2 + 64*QP2 + 64*VP2) * 4)   // 105472 B

__global__ __launch_bounds__(256)
void attn_mma_kernel(const float* __restrict__ q, const float* __restrict__ k,
                     const float* __restrict__ v, const float* __restrict__ mask,
                     float* __restrict__ out)
{
    extern __shared__ float sm[];
    float* Qs = sm;                       // [128][QP2]
    float* Ps = sm + 128 * QP2;           // [128][QP2]
    float* Ks = sm + 2 * 128 * QP2;       // [64][QP2]
    float* Vs = Ks + 64 * QP2;            // [64][VP2]

    int tid  = threadIdx.x;
    int lane = tid & 31;
    int wid  = tid >> 5;                  // 0..7
    int bth  = blockIdx.y;
    int bt   = bth / H_;
    int h    = bth % H_;
    int n0   = blockIdx.x * 128;
    size_t base = (size_t)bt * N_ * D_ + (size_t)h * HD_;

    // load Q tile [128][64] natural, tf32
    #pragma unroll
    for (int r = 0; r < 8; r++) {
        int e   = tid + r * 256;          // 0..2047
        int row = e >> 4;                 // 0..127
        int c4  = (e & 15) * 4;
        float4 val = make_float4(0.f, 0.f, 0.f, 0.f);
        int gn = n0 + row;
        if (gn < N_) val = *(const float4*)(q + base + (size_t)gn * D_ + c4);
        uint4 t;
        t.x = f2tf32(val.x); t.y = f2tf32(val.y);
        t.z = f2tf32(val.z); t.w = f2tf32(val.w);
        *(uint4*)&Qs[row * QP2 + c4] = t;
    }

    float oacc[8][4];
    #pragma unroll
    for (int ni = 0; ni < 8; ni++)
        #pragma unroll
        for (int r = 0; r < 4; r++) oacc[ni][r] = 0.f;
    float rs[2] = {0.f, 0.f};

    int qrow_frag = wid * 16 + (lane >> 2);
    int mrow_base = wid * 16 + (lane & 7) + ((lane >> 3) & 1) * 8;
    int kcol_sub  = (lane >> 4) * 4;
    // B ldmatrix lane coords for K (n-major tile, like GEMM W)
    int bn_sub = ((lane >> 4) & 1) * 8 + (lane & 7);
    int bk_sub = ((lane >> 3) & 1) * 4;
    int l2 = lane >> 2;
    int l4 = lane & 3;
    const float scale = 0.125f;

    for (int m0 = 0; m0 < 320; m0 += 64) {
        // K tile [kv][d] pitch 68, V tile pitch 72, tf32
        #pragma unroll
        for (int r = 0; r < 4; r++) {
            int e    = tid + r * 256;     // 0..1023
            int mrow = e >> 4;            // 0..63
            int d4   = (e & 15) * 4;
            int gm = m0 + mrow;
            float4 kv = make_float4(0.f, 0.f, 0.f, 0.f);
            float4 vv = make_float4(0.f, 0.f, 0.f, 0.f);
            if (gm < N_) {
                kv = *(const float4*)(k + base + (size_t)gm * D_ + d4);
                vv = *(const float4*)(v + base + (size_t)gm * D_ + d4);
            }
            uint4 tk, tv;
            tk.x = f2tf32(kv.x); tk.y = f2tf32(kv.y);
            tk.z = f2tf32(kv.z); tk.w = f2tf32(kv.w);
            tv.x = f2tf32(vv.x); tv.y = f2tf32(vv.y);
            tv.z = f2tf32(vv.z); tv.w = f2tf32(vv.w);
            *(uint4*)&Ks[mrow * QP2 + d4] = tk;
            *(uint4*)&Vs[mrow * VP2 + d4] = tv;
        }
        __syncthreads();

        // ---- S = Q @ K^T : A ldmatrix (Q rows), B ldmatrix (K n-major) ----
        float sacc[8][4];
        #pragma unroll
        for (int ni = 0; ni < 8; ni++)
            #pragma unroll
            for (int r = 0; r < 4; r++) sacc[ni][r] = 0.f;
        #pragma unroll
        for (int kk = 0; kk < 8; kk++) {
            uint32_t a[4];
            {
                uint32_t saddr = (uint32_t)__cvta_generic_to_shared(
                    &Qs[mrow_base * QP2 + kk * 8 + kcol_sub]);
                asm volatile(
                    "ldmatrix.sync.aligned.m8n8.x4.shared.b16 {%0,%1,%2,%3}, [%4];"
                    : "=r"(a[0]), "=r"(a[1]), "=r"(a[2]), "=r"(a[3])
                    : "r"(saddr));
            }
            uint32_t bfr[4][4];
            #pragma unroll
            for (int t = 0; t < 4; t++) {
                uint32_t saddr = (uint32_t)__cvta_generic_to_shared(
                    &Ks[(t * 16 + bn_sub) * QP2 + kk * 8 + bk_sub]);
                asm volatile(
                    "ldmatrix.sync.aligned.m8n8.x4.shared.b16 {%0,%1,%2,%3}, [%4];"
                    : "=r"(bfr[t][0]), "=r"(bfr[t][1]), "=r"(bfr[t][2]), "=r"(bfr[t][3])
                    : "r"(saddr));
            }
            #pragma unroll
            for (int ni = 0; ni < 8; ni++) {
                uint32_t b0 = bfr[ni >> 1][(ni & 1) * 2];
                uint32_t b1 = bfr[ni >> 1][(ni & 1) * 2 + 1];
                asm volatile(
                    "mma.sync.aligned.m16n8k8.row.col.f32.tf32.tf32.f32 "
                    "{%0,%1,%2,%3}, {%4,%5,%6,%7}, {%8,%9}, {%0,%1,%2,%3};"
                    : "+f"(sacc[ni][0]), "+f"(sacc[ni][1]),
                      "+f"(sacc[ni][2]), "+f"(sacc[ni][3])
                    : "r"(a[0]), "r"(a[1]), "r"(a[2]), "r"(a[3]),
                      "r"(b0), "r"(b1));
            }
        }

        // ---- single-pass: P = exp(S*scale*mask); rs += rowsum ----
        #pragma unroll
        for (int u = 0; u < 2; u++) {
            int rloc = qrow_frag + u * 8;
            int gr   = n0 + rloc;
            const float* mrow = mask + (size_t)(gr < N_ ? gr : 0) * MP + m0;
            float local = 0.f;
            #pragma unroll
            for (int ni = 0; ni < 8; ni++) {
                int c = ni * 8 + 2 * l4;
                float2 mv = *(const float2*)(mrow + c);
                float e0 = 0.f, e1 = 0.f;
                if (m0 + c     < N_) e0 = __expf(sacc[ni][2 * u + 0] * scale * mv.x);
                if (m0 + c + 1 < N_) e1 = __expf(sacc[ni][2 * u + 1] * scale * mv.y);
                local += e0 + e1;
                Ps[rloc * QP2 + c]     = __uint_as_float(f2tf32(e0));
                Ps[rloc * QP2 + c + 1] = __uint_as_float(f2tf32(e1));
            }
            rs[u] += local;
        }
        __syncwarp();   // Ps rows are warp-private

        // ---- O += P @ V : A ldmatrix (P rows), B scalar (V, conflict-free) ----
        #pragma unroll
        for (int kk = 0; kk < 8; kk++) {
            uint32_t a[4];
            uint32_t saddr = (uint32_t)__cvta_generic_to_shared(
                &Ps[mrow_base * QP2 + kk * 8 + kcol_sub]);
            asm volatile(
                "ldmatrix.sync.aligned.m8n8.x4.shared.b16 {%0,%1,%2,%3}, [%4];"
                : "=r"(a[0]), "=r"(a[1]), "=r"(a[2]), "=r"(a[3])
                : "r"(saddr));
            #pragma unroll
            for (int ni = 0; ni < 8; ni++) {
                uint32_t b0 = __float_as_uint(Vs[(kk * 8 + l4) * VP2 + ni * 8 + l2]);
                uint32_t b1 = __float_as_uint(Vs[(kk * 8 + l4 + 4) * VP2 + ni * 8 + l2]);
                asm volatile(
                    "mma.sync.aligned.m16n8k8.row.col.f32.tf32.tf32.f32 "
                    "{%0,%1,%2,%3}, {%4,%5,%6,%7}, {%8,%9}, {%0,%1,%2,%3};"
                    : "+f"(oacc[ni][0]), "+f"(oacc[ni][1]),
                      "+f"(oacc[ni][2]), "+f"(oacc[ni][3])
                    : "r"(a[0]), "r"(a[1]), "r"(a[2]), "r"(a[3]),
                      "r"(b0), "r"(b1));
            }
        }
        __syncthreads();   // all warps done with Ks/Vs before next tile
    }

    // epilogue
    #pragma unroll
    for (int u = 0; u < 2; u++) {
        rs[u] += __shfl_xor_sync(0xffffffffu, rs[u], 1);
        rs[u] += __shfl_xor_sync(0xffffffffu, rs[u], 2);
        int gr = n0 + qrow_frag + u * 8;
        if (gr >= N_) continue;
        float inv = 1.f / rs[u];
        #pragma unroll
        for (int ni = 0; ni < 8; ni++) {
            int dc = ni * 8 + 2 * l4;
            float2 o = make_float2(oacc[ni][2 * u] * inv, oacc[ni][2 * u + 1] * inv);
            *(float2*)(out + base + (size_t)gr * D_ + dc) = o;
        }
    }
}

// ---------------- launch ----------------
extern "C" void kernel_launch(void* const* d_in, const int* in_sizes, int n_in,
                              void* d_out, int out_size)
{
    const float* query = (const float*)d_in[0];
    const float* key   = (const float*)d_in[1];
    const float* value = (const float*)d_in[2];
    const float* sem   = (const float*)d_in[3];
    const float* Wq    = (const float*)d_in[4];
    const float* bq    = (const float*)d_in[5];
    const float* Wk    = (const float*)d_in[6];
    const float* bk    = (const float*)d_in[7];
    const float* Wv    = (const float*)d_in[8];
    const float* bv    = (const float*)d_in[9];
    const float* Wo    = (const float*)d_in[10];
    const float* bo    = (const float*)d_in[11];
    float* out = (float*)d_out;

    float *mask_p, *q_p, *k_p, *v_p, *attn_p, *wt_p;
    cudaGetSymbolAddress((void**)&mask_p, g_mask);
    cudaGetSymbolAddress((void**)&q_p,    g_q);
    cudaGetSymbolAddress((void**)&k_p,    g_k);
    cudaGetSymbolAddress((void**)&v_p,    g_v);
    cudaGetSymbolAddress((void**)&attn_p, g_attn);
    cudaGetSymbolAddress((void**)&wt_p,   g_wt);

    static bool attr_set = false;
    if (!attr_set) {
        cudaFuncSetAttribute(attn_mma_kernel,
                             cudaFuncAttributeMaxDynamicSharedMemorySize, ATTN_SMEM);
        cudaFuncSetAttribute(gemm_bias_tf32_kernel,
                             cudaFuncAttributeMaxDynamicSharedMemorySize, GEMM_SMEM);
        attr_set = true;
    }

    mask_softmax_kernel<<<N_, 256>>>(sem, mask_p);

    dim3 tg(D_ / 32, D_ / 32, 4);
    transpose_w_kernel<<<tg, dim3(32, 8)>>>(Wq, Wk, Wv, Wo, wt_p);

    dim3 g3(D_ / 128, (M_TOT + 127) / 128, 3);
    gemm_bias_tf32_kernel<<<g3, 256, GEMM_SMEM>>>(
        query, key, value, wt_p, bq, bk, bv, q_p, k_p, v_p, M_TOT);

    dim3 ga((N_ + 127) / 128, B_ * T_ * H_);
    attn_mma_kernel<<<ga, 256, ATTN_SMEM>>>(q_p, k_p, v_p, mask_p, attn_p);

    dim3 g1(D_ / 128, (M_TOT + 127) / 128, 1);
    gemm_bias_tf32_kernel<<<g1, 256, GEMM_SMEM>>>(
        attn_p, attn_p, attn_p, wt_p + 3 * (size_t)D_ * D_, bo, bo, bo,
        out, out, out, M_TOT);
}

// round 10
// speedup vs baseline: 6.1723x; 1.1665x over previous
#include <cuda_runtime.h>
#include <cuda_fp16.h>
#include <math.h>
#include <cstdint>

#define B_   8
#define T_   12
#define N_   307
#define D_   512
#define H_   8
#define HD_  64
#define M_TOT (B_*T_*N_)   // 29472
#define MP   320           // padded mask row pitch

// ---------------- device scratch (allocation-free rule) ----------------
__device__ float g_mask[N_*MP];
__device__ __half g_qh[M_TOT*D_];
__device__ __half g_kh[M_TOT*D_];
__device__ __half g_vh[M_TOT*D_];
__device__ float g_attn[M_TOT*D_];
__device__ float g_wt[4*D_*D_];     // transposed + tf32-rounded weights [N][K]

__device__ __forceinline__ uint32_t f2tf32(float x) {
    uint32_t y;
    asm("cvt.rna.tf32.f32 %0, %1;" : "=r"(y) : "f"(x));
    return y;
}
// packs (lo, hi) into f16x2 register {lo in bits[0:16), hi in bits[16:32)}
__device__ __forceinline__ uint32_t pack_f16x2(float lo, float hi) {
    uint32_t r;
    asm("cvt.rn.f16x2.f32 %0, %1, %2;" : "=r"(r) : "f"(hi), "f"(lo));
    return r;
}

// ---------------- mask = row-softmax(semantic_matrix), padded pitch ----
__global__ void mask_softmax_kernel(const float* __restrict__ sem,
                                    float* __restrict__ mask)
{
    int row = blockIdx.x;
    int tid = threadIdx.x;
    __shared__ float red[256];
    const float* x = sem + (size_t)row * N_;
    float v0 = (tid       < N_) ? x[tid]       : -INFINITY;
    float v1 = (tid + 256 < N_) ? x[tid + 256] : -INFINITY;
    red[tid] = fmaxf(v0, v1);
    __syncthreads();
    for (int s = 128; s > 0; s >>= 1) {
        if (tid < s) red[tid] = fmaxf(red[tid], red[tid + s]);
        __syncthreads();
    }
    float rowmax = red[0];
    __syncthreads();
    float e0 = (tid       < N_) ? __expf(v0 - rowmax) : 0.f;
    float e1 = (tid + 256 < N_) ? __expf(v1 - rowmax) : 0.f;
    red[tid] = e0 + e1;
    __syncthreads();
    for (int s = 128; s > 0; s >>= 1) {
        if (tid < s) red[tid] += red[tid + s];
        __syncthreads();
    }
    float inv = 1.f / red[0];
    if (tid       < N_) mask[(size_t)row * MP + tid]       = e0 * inv;
    if (tid + 256 < N_) mask[(size_t)row * MP + tid + 256] = e1 * inv;
    if (tid == 0)
        for (int c = N_; c < MP; c++) mask[(size_t)row * MP + c] = 0.f;
}

// ---------------- W -> W^T (tf32-rounded), 4 matrices ----------------
__global__ void transpose_w_kernel(const float* __restrict__ w0,
                                   const float* __restrict__ w1,
                                   const float* __restrict__ w2,
                                   const float* __restrict__ w3,
                                   float* __restrict__ wt)
{
    __shared__ float t[32][33];
    int z  = blockIdx.z;
    const float* src = (z == 0) ? w0 : (z == 1) ? w1 : (z == 2) ? w2 : w3;
    float* dst = wt + (size_t)z * D_ * D_;
    int tx = threadIdx.x, ty = threadIdx.y;
    int bx = blockIdx.x * 32, by = blockIdx.y * 32;
    #pragma unroll
    for (int i = 0; i < 32; i += 8)
        t[ty + i][tx] = src[(size_t)(by + ty + i) * D_ + bx + tx];
    __syncthreads();
    #pragma unroll
    for (int i = 0; i < 32; i += 8)
        dst[(size_t)(bx + ty + i) * D_ + by + tx] =
            __uint_as_float(f2tf32(t[tx][ty + i]));
}

// ---------------- tf32 mma.sync GEMM, optional fp16 output -------------
#define TILE_F  (128 * 36)
#define GEMM_SMEM (4 * TILE_F * 4)   // 73728 B

__global__ __launch_bounds__(256, 2)
void gemm_bias_tf32_kernel(const float* __restrict__ A0, const float* __restrict__ A1,
                           const float* __restrict__ A2, const float* __restrict__ WtB,
                           const float* __restrict__ b0p, const float* __restrict__ b1p,
                           const float* __restrict__ b2p,
                           void* __restrict__ C0, void* __restrict__ C1,
                           void* __restrict__ C2, int M, int f16_out)
{
    extern __shared__ float gsm[];
    int z = blockIdx.z;
    const float* A    = (z == 0) ? A0 : (z == 1) ? A1 : A2;
    const float* Wt   = WtB + (size_t)z * D_ * D_;
    const float* bias = (z == 0) ? b0p : (z == 1) ? b1p : b2p;
    void* Cv          = (z == 0) ? C0 : (z == 1) ? C1 : C2;

    int tid  = threadIdx.x;
    int lane = tid & 31;
    int wid  = tid >> 5;
    int warp_m = wid & 1;
    int warp_n = wid >> 1;
    int m0 = blockIdx.y * 128;
    int n0 = blockIdx.x * 128;

    float acc[4][4][4];
    #pragma unroll
    for (int mi = 0; mi < 4; mi++)
        #pragma unroll
        for (int ni = 0; ni < 4; ni++)
            #pragma unroll
            for (int r = 0; r < 4; r++) acc[mi][ni][r] = 0.f;

    float4 stA[4];

    auto ldg_A = [&](int k0) {
        #pragma unroll
        for (int r = 0; r < 4; r++) {
            int e  = tid + r * 256;
            int am = e >> 3;
            int ak = (e & 7) * 4;
            int gm = m0 + am;
            stA[r] = (gm < M) ? *(const float4*)(A + (size_t)gm * D_ + k0 + ak)
                              : make_float4(0.f, 0.f, 0.f, 0.f);
        }
    };
    auto sts_A = [&](int b) {
        float* Ab = gsm + b * 2 * TILE_F;
        #pragma unroll
        for (int r = 0; r < 4; r++) {
            int e  = tid + r * 256;
            int am = e >> 3;
            int ak = (e & 7) * 4;
            uint4 v;
            v.x = f2tf32(stA[r].x); v.y = f2tf32(stA[r].y);
            v.z = f2tf32(stA[r].z); v.w = f2tf32(stA[r].w);
            *(uint4*)&Ab[am * 36 + ak] = v;
        }
    };
    auto cpa_W = [&](int b, int k0) {
        float* Wb = gsm + b * 2 * TILE_F + TILE_F;
        #pragma unroll
        for (int r = 0; r < 4; r++) {
            int e   = tid + r * 256;
            int row = e >> 3;
            int c4  = (e & 7) * 4;
            uint32_t dst = (uint32_t)__cvta_generic_to_shared(&Wb[row * 36 + c4]);
            const float* src = Wt + (size_t)(n0 + row) * D_ + k0 + c4;
            asm volatile("cp.async.ca.shared.global [%0], [%1], 16;"
                         :: "r"(dst), "l"(src));
        }
        asm volatile("cp.async.commit_group;");
    };

    ldg_A(0);
    cpa_W(0, 0);
    sts_A(0);
    asm volatile("cp.async.wait_group 0;");
    __syncthreads();

    int mrow_base = warp_m * 64 + (lane & 7) + ((lane >> 3) & 1) * 8;
    int kcol_sub  = (lane >> 4) * 4;
    int bn_row = warp_n * 32 + ((lane >> 4) & 1) * 8 + (lane & 7);
    int bk_sub = ((lane >> 3) & 1) * 4;

    int buf = 0;
    for (int k0 = 0; k0 < D_; k0 += 32) {
        bool last = (k0 == D_ - 32);
        if (!last) {
            ldg_A(k0 + 32);
            cpa_W(buf ^ 1, k0 + 32);
        }

        float* Ab = gsm + buf * 2 * TILE_F;
        float* Wb = Ab + TILE_F;
        #pragma unroll
        for (int kk = 0; kk < 4; kk++) {
            uint32_t a[4][4];
            #pragma unroll
            for (int mi = 0; mi < 4; mi++) {
                uint32_t saddr = (uint32_t)__cvta_generic_to_shared(
                    &Ab[(mrow_base + mi * 16) * 36 + kk * 8 + kcol_sub]);
                asm volatile(
                    "ldmatrix.sync.aligned.m8n8.x4.shared.b16 {%0,%1,%2,%3}, [%4];"
                    : "=r"(a[mi][0]), "=r"(a[mi][1]), "=r"(a[mi][2]), "=r"(a[mi][3])
                    : "r"(saddr));
            }
            uint32_t bfr[2][4];
            #pragma unroll
            for (int t = 0; t < 2; t++) {
                uint32_t saddr = (uint32_t)__cvta_generic_to_shared(
                    &Wb[(bn_row + t * 16) * 36 + kk * 8 + bk_sub]);
                asm volatile(
                    "ldmatrix.sync.aligned.m8n8.x4.shared.b16 {%0,%1,%2,%3}, [%4];"
                    : "=r"(bfr[t][0]), "=r"(bfr[t][1]), "=r"(bfr[t][2]), "=r"(bfr[t][3])
                    : "r"(saddr));
            }
            #pragma unroll
            for (int ni = 0; ni < 4; ni++) {
                uint32_t b0 = bfr[ni >> 1][(ni & 1) * 2];
                uint32_t b1 = bfr[ni >> 1][(ni & 1) * 2 + 1];
                #pragma unroll
                for (int mi = 0; mi < 4; mi++) {
                    asm volatile(
                        "mma.sync.aligned.m16n8k8.row.col.f32.tf32.tf32.f32 "
                        "{%0,%1,%2,%3}, {%4,%5,%6,%7}, {%8,%9}, {%0,%1,%2,%3};"
                        : "+f"(acc[mi][ni][0]), "+f"(acc[mi][ni][1]),
                          "+f"(acc[mi][ni][2]), "+f"(acc[mi][ni][3])
                        : "r"(a[mi][0]), "r"(a[mi][1]), "r"(a[mi][2]), "r"(a[mi][3]),
                          "r"(b0), "r"(b1));
                }
            }
        }
        if (!last) {
            sts_A(buf ^ 1);
            asm volatile("cp.async.wait_group 0;");
            __syncthreads();
            buf ^= 1;
        }
    }

    int crow = m0 + warp_m * 64 + (lane >> 2);
    int ccol0 = n0 + warp_n * 32 + 2 * (lane & 3);
    #pragma unroll
    for (int mi = 0; mi < 4; mi++) {
        int r0 = crow + mi * 16;
        #pragma unroll
        for (int ni = 0; ni < 4; ni++) {
            int cc = ccol0 + ni * 8;
            float bb0 = bias[cc], bb1 = bias[cc + 1];
            if (f16_out) {
                __half* C = (__half*)Cv;
                if (r0 < M)
                    *(uint32_t*)(C + (size_t)r0 * D_ + cc) =
                        pack_f16x2(acc[mi][ni][0] + bb0, acc[mi][ni][1] + bb1);
                if (r0 + 8 < M)
                    *(uint32_t*)(C + (size_t)(r0 + 8) * D_ + cc) =
                        pack_f16x2(acc[mi][ni][2] + bb0, acc[mi][ni][3] + bb1);
            } else {
                float* C = (float*)Cv;
                if (r0 < M) {
                    float2 o = make_float2(acc[mi][ni][0] + bb0, acc[mi][ni][1] + bb1);
                    *(float2*)(C + (size_t)r0 * D_ + cc) = o;
                }
                if (r0 + 8 < M) {
                    float2 o = make_float2(acc[mi][ni][2] + bb0, acc[mi][ni][3] + bb1);
                    *(float2*)(C + (size_t)(r0 + 8) * D_ + cc) = o;
                }
            }
        }
    }
}

// ---------------- fp16 flash attention (m16n8k16) ----------------
// 256 thr / 8 warps, q-tile 128 rows, warp = m16 x n64. All tiles fp16
// (10 mantissa bits = tf32-equivalent relative precision; values O(1)).
// pitch PB=72 halves (144B = 9x16B -> ldmatrix conflict-free).
// K/V double-buffered cp.async. P packed f16x2.
#define PB 72
#define ATTN_SMEM ((2*128*PB + 4*64*PB) * 2)   // 73728 B

__global__ __launch_bounds__(256, 2)
void attn_mma_kernel(const __half* __restrict__ q,
                     const __half* __restrict__ k,
                     const __half* __restrict__ v,
                     const float* __restrict__ mask,
                     float* __restrict__ out)
{
    extern __shared__ char smc[];
    uint32_t sb = (uint32_t)__cvta_generic_to_shared(smc);
    const uint32_t sQ = sb;
    const uint32_t sP = sb + 128 * PB * 2;
    const uint32_t sK0 = sb + 2 * 128 * PB * 2;          // [2][64*PB]
    const uint32_t sV0 = sK0 + 2 * 64 * PB * 2;          // [2][64*PB]

    int tid  = threadIdx.x;
    int lane = tid & 31;
    int wid  = tid >> 5;                 // 0..7
    int bth  = blockIdx.y;
    int bt   = bth / H_;
    int h    = bth % H_;
    int n0   = blockIdx.x * 128;
    size_t gbase = (size_t)bt * N_ * D_ + (size_t)h * HD_;

    // ---- Q tile via cp.async (zero-fill OOB rows) ----
    #pragma unroll
    for (int r = 0; r < 4; r++) {
        int e    = tid + r * 256;        // 0..1023
        int row  = e >> 3;               // 0..127
        int cseg = e & 7;                // 16B segment
        int gn = n0 + row;
        const __half* src = q + gbase + (size_t)(gn < N_ ? gn : 0) * D_ + cseg * 8;
        uint32_t dst = sQ + (row * PB + cseg * 8) * 2;
        int sz = (gn < N_) ? 16 : 0;
        asm volatile("cp.async.ca.shared.global [%0], [%1], 16, %2;"
                     :: "r"(dst), "l"(src), "r"(sz));
    }
    // ---- K/V tile loader ----
    auto load_kv = [&](int m0, int buf) {
        uint32_t kdst0 = sK0 + buf * 64 * PB * 2;
        uint32_t vdst0 = sV0 + buf * 64 * PB * 2;
        #pragma unroll
        for (int r = 0; r < 2; r++) {
            int e    = tid + r * 256;    // 0..511
            int row  = e >> 3;           // 0..63
            int cseg = e & 7;
            int gm = m0 + row;
            size_t goff = gbase + (size_t)(gm < N_ ? gm : 0) * D_ + cseg * 8;
            int sz = (gm < N_) ? 16 : 0;
            uint32_t kd = kdst0 + (row * PB + cseg * 8) * 2;
            uint32_t vd = vdst0 + (row * PB + cseg * 8) * 2;
            asm volatile("cp.async.ca.shared.global [%0], [%1], 16, %2;"
                         :: "r"(kd), "l"(k + goff), "r"(sz));
            asm volatile("cp.async.ca.shared.global [%0], [%1], 16, %2;"
                         :: "r"(vd), "l"(v + goff), "r"(sz));
        }
        asm volatile("cp.async.commit_group;");
    };

    load_kv(0, 0);   // group 0 (Q rides the same wait)

    float oacc[8][4];
    #pragma unroll
    for (int ni = 0; ni < 8; ni++)
        #pragma unroll
        for (int r = 0; r < 4; r++) oacc[ni][r] = 0.f;
    float rs[2] = {0.f, 0.f};

    int qrow_frag = wid * 16 + (lane >> 2);
    // ldmatrix lane addressing
    int arow  = wid * 16 + (lane & 15);
    int acol8 = (lane >> 4) * 8;                       // elems
    int brow  = (lane & 7) + ((lane >> 3) & 1) * 8;
    int bcol8 = (lane >> 4) * 8;
    int l4 = lane & 3;
    const float scale = 0.125f;

    int buf = 0;
    for (int it = 0; it < 5; it++) {
        int m0 = it * 64;
        if (it < 4) load_kv(m0 + 64, buf ^ 1);
        if (it < 4) asm volatile("cp.async.wait_group 1;");
        else        asm volatile("cp.async.wait_group 0;");
        __syncthreads();

        uint32_t sK = sK0 + buf * 64 * PB * 2;
        uint32_t sV = sV0 + buf * 64 * PB * 2;

        // ---- S = Q @ K^T (fp16 m16n8k16) ----
        float sacc[8][4];
        #pragma unroll
        for (int ni = 0; ni < 8; ni++)
            #pragma unroll
            for (int r = 0; r < 4; r++) sacc[ni][r] = 0.f;
        #pragma unroll
        for (int kk = 0; kk < 4; kk++) {           // d k-steps of 16
            uint32_t a[4];
            uint32_t sa = sQ + (arow * PB + kk * 16 + acol8) * 2;
            asm volatile(
                "ldmatrix.sync.aligned.m8n8.x4.shared.b16 {%0,%1,%2,%3}, [%4];"
                : "=r"(a[0]), "=r"(a[1]), "=r"(a[2]), "=r"(a[3]) : "r"(sa));
            uint32_t bfr[4][4];
            #pragma unroll
            for (int t = 0; t < 4; t++) {          // kv n-tile pairs
                uint32_t sbb = sK + ((t * 16 + brow) * PB + kk * 16 + bcol8) * 2;
                asm volatile(
                    "ldmatrix.sync.aligned.m8n8.x4.shared.b16 {%0,%1,%2,%3}, [%4];"
                    : "=r"(bfr[t][0]), "=r"(bfr[t][1]), "=r"(bfr[t][2]), "=r"(bfr[t][3])
                    : "r"(sbb));
            }
            #pragma unroll
            for (int ni = 0; ni < 8; ni++) {
                uint32_t b0 = bfr[ni >> 1][ni & 1];        // n-rows sel by bit3
                uint32_t b1 = bfr[ni >> 1][(ni & 1) + 2];  // k+8 sel by bit4
                asm volatile(
                    "mma.sync.aligned.m16n8k16.row.col.f32.f16.f16.f32 "
                    "{%0,%1,%2,%3}, {%4,%5,%6,%7}, {%8,%9}, {%0,%1,%2,%3};"
                    : "+f"(sacc[ni][0]), "+f"(sacc[ni][1]),
                      "+f"(sacc[ni][2]), "+f"(sacc[ni][3])
                    : "r"(a[0]), "r"(a[1]), "r"(a[2]), "r"(a[3]),
                      "r"(b0), "r"(b1));
            }
        }

        // ---- P = exp(S*scale*mask) -> f16 pairs; rs += rowsum ----
        #pragma unroll
        for (int u = 0; u < 2; u++) {
            int rloc = qrow_frag + u * 8;
            int gr   = n0 + rloc;
            const float* mrow = mask + (size_t)(gr < N_ ? gr : 0) * MP + m0;
            float local = 0.f;
            #pragma unroll
            for (int ni = 0; ni < 8; ni++) {
                int c = ni * 8 + 2 * l4;
                float2 mv = *(const float2*)(mrow + c);
                float e0 = 0.f, e1 = 0.f;
                if (m0 + c     < N_) e0 = __expf(sacc[ni][2 * u + 0] * scale * mv.x);
                if (m0 + c + 1 < N_) e1 = __expf(sacc[ni][2 * u + 1] * scale * mv.y);
                local += e0 + e1;
                uint32_t pk = pack_f16x2(e0, e1);
                uint32_t pd = sP + (rloc * PB + c) * 2;
                asm volatile("st.shared.b32 [%0], %1;" :: "r"(pd), "r"(pk));
            }
            rs[u] += local;
        }
        __syncwarp();   // P rows are warp-private

        // ---- O += P @ V (V via ldmatrix.trans) ----
        #pragma unroll
        for (int kk = 0; kk < 4; kk++) {           // kv k-steps of 16
            uint32_t a[4];
            uint32_t sa = sP + (arow * PB + kk * 16 + acol8) * 2;
            asm volatile(
                "ldmatrix.sync.aligned.m8n8.x4.shared.b16 {%0,%1,%2,%3}, [%4];"
                : "=r"(a[0]), "=r"(a[1]), "=r"(a[2]), "=r"(a[3]) : "r"(sa));
            uint32_t bfr[4][4];
            #pragma unroll
            for (int t = 0; t < 4; t++) {          // d n-tile pairs
                uint32_t sbb = sV + ((kk * 16 + brow) * PB + t * 16 + bcol8) * 2;
                asm volatile(
                    "ldmatrix.sync.aligned.m8n8.x4.trans.shared.b16 {%0,%1,%2,%3}, [%4];"
                    : "=r"(bfr[t][0]), "=r"(bfr[t][1]), "=r"(bfr[t][2]), "=r"(bfr[t][3])
                    : "r"(sbb));
            }
            #pragma unroll
            for (int ni = 0; ni < 8; ni++) {
                uint32_t b0 = bfr[ni >> 1][(ni & 1) * 2];      // n sel by bit4
                uint32_t b1 = bfr[ni >> 1][(ni & 1) * 2 + 1];  // k+8 sel by bit3
                asm volatile(
                    "mma.sync.aligned.m16n8k16.row.col.f32.f16.f16.f32 "
                    "{%0,%1,%2,%3}, {%4,%5,%6,%7}, {%8,%9}, {%0,%1,%2,%3};"
                    : "+f"(oacc[ni][0]), "+f"(oacc[ni][1]),
                      "+f"(oacc[ni][2]), "+f"(oacc[ni][3])
                    : "r"(a[0]), "r"(a[1]), "r"(a[2]), "r"(a[3]),
                      "r"(b0), "r"(b1));
            }
        }
        __syncthreads();   // all warps done with K/V buf before overwrite
        buf ^= 1;
    }

    // epilogue: reduce row sums across quad, normalize, store fp32
    #pragma unroll
    for (int u = 0; u < 2; u++) {
        rs[u] += __shfl_xor_sync(0xffffffffu, rs[u], 1);
        rs[u] += __shfl_xor_sync(0xffffffffu, rs[u], 2);
        int gr = n0 + qrow_frag + u * 8;
        if (gr >= N_) continue;
        float inv = 1.f / rs[u];
        #pragma unroll
        for (int ni = 0; ni < 8; ni++) {
            int dc = ni * 8 + 2 * l4;
            float2 o = make_float2(oacc[ni][2 * u] * inv, oacc[ni][2 * u + 1] * inv);
            *(float2*)(out + gbase + (size_t)gr * D_ + dc) = o;
        }
    }
}

// ---------------- launch ----------------
extern "C" void kernel_launch(void* const* d_in, const int* in_sizes, int n_in,
                              void* d_out, int out_size)
{
    const float* query = (const float*)d_in[0];
    const float* key   = (const float*)d_in[1];
    const float* value = (const float*)d_in[2];
    const float* sem   = (const float*)d_in[3];
    const float* Wq    = (const float*)d_in[4];
    const float* bq    = (const float*)d_in[5];
    const float* Wk    = (const float*)d_in[6];
    const float* bk    = (const float*)d_in[7];
    const float* Wv    = (const float*)d_in[8];
    const float* bv    = (const float*)d_in[9];
    const float* Wo    = (const float*)d_in[10];
    const float* bo    = (const float*)d_in[11];
    float* out = (float*)d_out;

    float *mask_p, *attn_p, *wt_p;
    __half *qh_p, *kh_p, *vh_p;
    cudaGetSymbolAddress((void**)&mask_p, g_mask);
    cudaGetSymbolAddress((void**)&qh_p,   g_qh);
    cudaGetSymbolAddress((void**)&kh_p,   g_kh);
    cudaGetSymbolAddress((void**)&vh_p,   g_vh);
    cudaGetSymbolAddress((void**)&attn_p, g_attn);
    cudaGetSymbolAddress((void**)&wt_p,   g_wt);

    static bool attr_set = false;
    if (!attr_set) {
        cudaFuncSetAttribute(attn_mma_kernel,
                             cudaFuncAttributeMaxDynamicSharedMemorySize, ATTN_SMEM);
        cudaFuncSetAttribute(gemm_bias_tf32_kernel,
                             cudaFuncAttributeMaxDynamicSharedMemorySize, GEMM_SMEM);
        attr_set = true;
    }

    mask_softmax_kernel<<<N_, 256>>>(sem, mask_p);

    dim3 tg(D_ / 32, D_ / 32, 4);
    transpose_w_kernel<<<tg, dim3(32, 8)>>>(Wq, Wk, Wv, Wo, wt_p);

    // fused Q/K/V projections -> fp16 outputs
    dim3 g3(D_ / 128, (M_TOT + 127) / 128, 3);
    gemm_bias_tf32_kernel<<<g3, 256, GEMM_SMEM>>>(
        query, key, value, wt_p, bq, bk, bv, qh_p, kh_p, vh_p, M_TOT, 1);

    dim3 ga((N_ + 127) / 128, B_ * T_ * H_);
    attn_mma_kernel<<<ga, 256, ATTN_SMEM>>>(qh_p, kh_p, vh_p, mask_p, attn_p);

    // output projection (fp32 in/out)
    dim3 g1(D_ / 128, (M_TOT + 127) / 128, 1);
    gemm_bias_tf32_kernel<<<g1, 256, GEMM_SMEM>>>(
        attn_p, attn_p, attn_p, wt_p + 3 * (size_t)D_ * D_, bo, bo, bo,
        out, out, out, M_TOT, 0);
}

// round 11
// speedup vs baseline: 7.8945x; 1.2790x over previous
#include <cuda_runtime.h>
#include <cuda_fp16.h>
#include <math.h>
#include <cstdint>

#define B_   8
#define T_   12
#define N_   307
#define D_   512
#define H_   8
#define HD_  64
#define M_TOT (B_*T_*N_)   // 29472
#define MP   320           // padded mask row pitch

// ---------------- device scratch (allocation-free rule) ----------------
__device__ float g_mask[N_*MP];
__device__ __half g_qh[M_TOT*D_];
__device__ __half g_kh[M_TOT*D_];
__device__ __half g_vh[M_TOT*D_];
__device__ float g_attn[M_TOT*D_];
__device__ __half g_wt[4*D_*D_];    // transposed fp16 weights [N][K]

// packs (lo, hi) into f16x2 register {lo in bits[0:16), hi in bits[16:32)}
__device__ __forceinline__ uint32_t pack_f16x2(float lo, float hi) {
    uint32_t r;
    asm("cvt.rn.f16x2.f32 %0, %1, %2;" : "=r"(r) : "f"(hi), "f"(lo));
    return r;
}

// ---------------- mask = row-softmax(semantic_matrix), padded pitch ----
__global__ void mask_softmax_kernel(const float* __restrict__ sem,
                                    float* __restrict__ mask)
{
    int row = blockIdx.x;
    int tid = threadIdx.x;
    __shared__ float red[256];
    const float* x = sem + (size_t)row * N_;
    float v0 = (tid       < N_) ? x[tid]       : -INFINITY;
    float v1 = (tid + 256 < N_) ? x[tid + 256] : -INFINITY;
    red[tid] = fmaxf(v0, v1);
    __syncthreads();
    for (int s = 128; s > 0; s >>= 1) {
        if (tid < s) red[tid] = fmaxf(red[tid], red[tid + s]);
        __syncthreads();
    }
    float rowmax = red[0];
    __syncthreads();
    float e0 = (tid       < N_) ? __expf(v0 - rowmax) : 0.f;
    float e1 = (tid + 256 < N_) ? __expf(v1 - rowmax) : 0.f;
    red[tid] = e0 + e1;
    __syncthreads();
    for (int s = 128; s > 0; s >>= 1) {
        if (tid < s) red[tid] += red[tid + s];
        __syncthreads();
    }
    float inv = 1.f / red[0];
    if (tid       < N_) mask[(size_t)row * MP + tid]       = e0 * inv;
    if (tid + 256 < N_) mask[(size_t)row * MP + tid + 256] = e1 * inv;
    if (tid == 0)
        for (int c = N_; c < MP; c++) mask[(size_t)row * MP + c] = 0.f;
}

// ---------------- W -> W^T (fp16), 4 matrices ----------------
__global__ void transpose_w_kernel(const float* __restrict__ w0,
                                   const float* __restrict__ w1,
                                   const float* __restrict__ w2,
                                   const float* __restrict__ w3,
                                   __half* __restrict__ wt)
{
    __shared__ float t[32][33];
    int z  = blockIdx.z;
    const float* src = (z == 0) ? w0 : (z == 1) ? w1 : (z == 2) ? w2 : w3;
    __half* dst = wt + (size_t)z * D_ * D_;
    int tx = threadIdx.x, ty = threadIdx.y;
    int bx = blockIdx.x * 32, by = blockIdx.y * 32;
    #pragma unroll
    for (int i = 0; i < 32; i += 8)
        t[ty + i][tx] = src[(size_t)(by + ty + i) * D_ + bx + tx];
    __syncthreads();
    #pragma unroll
    for (int i = 0; i < 32; i += 8)
        dst[(size_t)(bx + ty + i) * D_ + by + tx] = __float2half(t[tx][ty + i]);
}

// ---------------- fp16 mma.sync GEMM (m16n8k16) -----------------------
// tiles: 128x128x64, 256 thr = 8 warps (2m x 4n). A/W smem fp16, pitch 72
// halves (144B = 9x16B, conflict-free ldmatrix — validated in attention).
// A: fp32 global -> fp16 smem. W: fp16 global via cp.async. fp32 acc.
#define GP 72
#define TILE_H (128 * GP)                 // halves per tile
#define GEMM_SMEM (4 * TILE_H * 2)        // 2 bufs x (A + W) = 73728 B

__global__ __launch_bounds__(256, 2)
void gemm_bias_f16_kernel(const float* __restrict__ A0, const float* __restrict__ A1,
                          const float* __restrict__ A2, const __half* __restrict__ WtB,
                          const float* __restrict__ b0p, const float* __restrict__ b1p,
                          const float* __restrict__ b2p,
                          void* __restrict__ C0, void* __restrict__ C1,
                          void* __restrict__ C2, int M, int f16_out)
{
    extern __shared__ __half gsh[];
    int z = blockIdx.z;
    const float* A     = (z == 0) ? A0 : (z == 1) ? A1 : A2;
    const __half* Wt   = WtB + (size_t)z * D_ * D_;
    const float* bias  = (z == 0) ? b0p : (z == 1) ? b1p : b2p;
    void* Cv           = (z == 0) ? C0 : (z == 1) ? C1 : C2;

    int tid  = threadIdx.x;
    int lane = tid & 31;
    int wid  = tid >> 5;
    int warp_m = wid & 1;
    int warp_n = wid >> 1;
    int m0 = blockIdx.y * 128;
    int n0 = blockIdx.x * 128;

    float acc[4][4][4];
    #pragma unroll
    for (int mi = 0; mi < 4; mi++)
        #pragma unroll
        for (int ni = 0; ni < 4; ni++)
            #pragma unroll
            for (int r = 0; r < 4; r++) acc[mi][ni][r] = 0.f;

    float4 stA[4][2];

    // A slab: 128 rows x 64 fp32 -> regs (thread: row e>>3, seg e&7 of 8 floats)
    auto ldg_A = [&](int k0) {
        #pragma unroll
        for (int r = 0; r < 4; r++) {
            int e   = tid + r * 256;       // 0..1023
            int row = e >> 3;              // 0..127
            int seg = e & 7;               // 8-float segment
            int gm = m0 + row;
            if (gm < M) {
                const float* src = A + (size_t)gm * D_ + k0 + seg * 8;
                stA[r][0] = *(const float4*)(src);
                stA[r][1] = *(const float4*)(src + 4);
            } else {
                stA[r][0] = make_float4(0.f, 0.f, 0.f, 0.f);
                stA[r][1] = make_float4(0.f, 0.f, 0.f, 0.f);
            }
        }
    };
    auto sts_A = [&](int b) {
        __half* Ab = gsh + b * 2 * TILE_H;
        #pragma unroll
        for (int r = 0; r < 4; r++) {
            int e   = tid + r * 256;
            int row = e >> 3;
            int seg = e & 7;
            uint4 p;
            p.x = pack_f16x2(stA[r][0].x, stA[r][0].y);
            p.y = pack_f16x2(stA[r][0].z, stA[r][0].w);
            p.z = pack_f16x2(stA[r][1].x, stA[r][1].y);
            p.w = pack_f16x2(stA[r][1].z, stA[r][1].w);
            *(uint4*)(Ab + row * GP + seg * 8) = p;
        }
    };
    // W slab: 128 rows x 64 fp16 via cp.async
    auto cpa_W = [&](int b, int k0) {
        __half* Wb = gsh + b * 2 * TILE_H + TILE_H;
        #pragma unroll
        for (int r = 0; r < 4; r++) {
            int e   = tid + r * 256;
            int row = e >> 3;
            int seg = e & 7;
            uint32_t dst = (uint32_t)__cvta_generic_to_shared(Wb + row * GP + seg * 8);
            const __half* src = Wt + (size_t)(n0 + row) * D_ + k0 + seg * 8;
            asm volatile("cp.async.ca.shared.global [%0], [%1], 16;"
                         :: "r"(dst), "l"(src));
        }
        asm volatile("cp.async.commit_group;");
    };

    ldg_A(0);
    cpa_W(0, 0);
    sts_A(0);
    asm volatile("cp.async.wait_group 0;");
    __syncthreads();

    // fragment lane addressing (identical to attention's validated mapping)
    int arow_sub = lane & 15;
    int acol8    = (lane >> 4) * 8;
    int brow_sub = (lane & 7) + ((lane >> 3) & 1) * 8;
    int bcol8    = (lane >> 4) * 8;

    int buf = 0;
    for (int k0 = 0; k0 < D_; k0 += 64) {
        bool last = (k0 == D_ - 64);
        if (!last) {
            ldg_A(k0 + 64);
            cpa_W(buf ^ 1, k0 + 64);
        }

        __half* Ab = gsh + buf * 2 * TILE_H;
        __half* Wb = Ab + TILE_H;
        #pragma unroll
        for (int kk = 0; kk < 4; kk++) {          // k-steps of 16
            uint32_t a[4][4];
            #pragma unroll
            for (int mi = 0; mi < 4; mi++) {
                uint32_t sa = (uint32_t)__cvta_generic_to_shared(
                    Ab + (warp_m * 64 + mi * 16 + arow_sub) * GP + kk * 16 + acol8);
                asm volatile(
                    "ldmatrix.sync.aligned.m8n8.x4.shared.b16 {%0,%1,%2,%3}, [%4];"
                    : "=r"(a[mi][0]), "=r"(a[mi][1]), "=r"(a[mi][2]), "=r"(a[mi][3])
                    : "r"(sa));
            }
            uint32_t bfr[2][4];
            #pragma unroll
            for (int t = 0; t < 2; t++) {
                uint32_t sbb = (uint32_t)__cvta_generic_to_shared(
                    Wb + (warp_n * 32 + t * 16 + brow_sub) * GP + kk * 16 + bcol8);
                asm volatile(
                    "ldmatrix.sync.aligned.m8n8.x4.shared.b16 {%0,%1,%2,%3}, [%4];"
                    : "=r"(bfr[t][0]), "=r"(bfr[t][1]), "=r"(bfr[t][2]), "=r"(bfr[t][3])
                    : "r"(sbb));
            }
            #pragma unroll
            for (int ni = 0; ni < 4; ni++) {
                uint32_t b0 = bfr[ni >> 1][ni & 1];
                uint32_t b1 = bfr[ni >> 1][(ni & 1) + 2];
                #pragma unroll
                for (int mi = 0; mi < 4; mi++) {
                    asm volatile(
                        "mma.sync.aligned.m16n8k16.row.col.f32.f16.f16.f32 "
                        "{%0,%1,%2,%3}, {%4,%5,%6,%7}, {%8,%9}, {%0,%1,%2,%3};"
                        : "+f"(acc[mi][ni][0]), "+f"(acc[mi][ni][1]),
                          "+f"(acc[mi][ni][2]), "+f"(acc[mi][ni][3])
                        : "r"(a[mi][0]), "r"(a[mi][1]), "r"(a[mi][2]), "r"(a[mi][3]),
                          "r"(b0), "r"(b1));
                }
            }
        }
        if (!last) {
            sts_A(buf ^ 1);
            asm volatile("cp.async.wait_group 0;");
            __syncthreads();
            buf ^= 1;
        }
    }

    int crow = m0 + warp_m * 64 + (lane >> 2);
    int ccol0 = n0 + warp_n * 32 + 2 * (lane & 3);
    #pragma unroll
    for (int mi = 0; mi < 4; mi++) {
        int r0 = crow + mi * 16;
        #pragma unroll
        for (int ni = 0; ni < 4; ni++) {
            int cc = ccol0 + ni * 8;
            float bb0 = bias[cc], bb1 = bias[cc + 1];
            if (f16_out) {
                __half* C = (__half*)Cv;
                if (r0 < M)
                    *(uint32_t*)(C + (size_t)r0 * D_ + cc) =
                        pack_f16x2(acc[mi][ni][0] + bb0, acc[mi][ni][1] + bb1);
                if (r0 + 8 < M)
                    *(uint32_t*)(C + (size_t)(r0 + 8) * D_ + cc) =
                        pack_f16x2(acc[mi][ni][2] + bb0, acc[mi][ni][3] + bb1);
            } else {
                float* C = (float*)Cv;
                if (r0 < M) {
                    float2 o = make_float2(acc[mi][ni][0] + bb0, acc[mi][ni][1] + bb1);
                    *(float2*)(C + (size_t)r0 * D_ + cc) = o;
                }
                if (r0 + 8 < M) {
                    float2 o = make_float2(acc[mi][ni][2] + bb0, acc[mi][ni][3] + bb1);
                    *(float2*)(C + (size_t)(r0 + 8) * D_ + cc) = o;
                }
            }
        }
    }
}

// ---------------- fp16 flash attention (m16n8k16) — unchanged R10 ------
#define PB 72
#define ATTN_SMEM ((2*128*PB + 4*64*PB) * 2)   // 73728 B

__global__ __launch_bounds__(256, 2)
void attn_mma_kernel(const __half* __restrict__ q,
                     const __half* __restrict__ k,
                     const __half* __restrict__ v,
                     const float* __restrict__ mask,
                     float* __restrict__ out)
{
    extern __shared__ char smc[];
    uint32_t sb = (uint32_t)__cvta_generic_to_shared(smc);
    const uint32_t sQ = sb;
    const uint32_t sP = sb + 128 * PB * 2;
    const uint32_t sK0 = sb + 2 * 128 * PB * 2;          // [2][64*PB]
    const uint32_t sV0 = sK0 + 2 * 64 * PB * 2;          // [2][64*PB]

    int tid  = threadIdx.x;
    int lane = tid & 31;
    int wid  = tid >> 5;                 // 0..7
    int bth  = blockIdx.y;
    int bt   = bth / H_;
    int h    = bth % H_;
    int n0   = blockIdx.x * 128;
    size_t gbase = (size_t)bt * N_ * D_ + (size_t)h * HD_;

    #pragma unroll
    for (int r = 0; r < 4; r++) {
        int e    = tid + r * 256;
        int row  = e >> 3;
        int cseg = e & 7;
        int gn = n0 + row;
        const __half* src = q + gbase + (size_t)(gn < N_ ? gn : 0) * D_ + cseg * 8;
        uint32_t dst = sQ + (row * PB + cseg * 8) * 2;
        int sz = (gn < N_) ? 16 : 0;
        asm volatile("cp.async.ca.shared.global [%0], [%1], 16, %2;"
                     :: "r"(dst), "l"(src), "r"(sz));
    }
    auto load_kv = [&](int m0, int buf) {
        uint32_t kdst0 = sK0 + buf * 64 * PB * 2;
        uint32_t vdst0 = sV0 + buf * 64 * PB * 2;
        #pragma unroll
        for (int r = 0; r < 2; r++) {
            int e    = tid + r * 256;
            int row  = e >> 3;
            int cseg = e & 7;
            int gm = m0 + row;
            size_t goff = gbase + (size_t)(gm < N_ ? gm : 0) * D_ + cseg * 8;
            int sz = (gm < N_) ? 16 : 0;
            uint32_t kd = kdst0 + (row * PB + cseg * 8) * 2;
            uint32_t vd = vdst0 + (row * PB + cseg * 8) * 2;
            asm volatile("cp.async.ca.shared.global [%0], [%1], 16, %2;"
                         :: "r"(kd), "l"(k + goff), "r"(sz));
            asm volatile("cp.async.ca.shared.global [%0], [%1], 16, %2;"
                         :: "r"(vd), "l"(v + goff), "r"(sz));
        }
        asm volatile("cp.async.commit_group;");
    };

    load_kv(0, 0);

    float oacc[8][4];
    #pragma unroll
    for (int ni = 0; ni < 8; ni++)
        #pragma unroll
        for (int r = 0; r < 4; r++) oacc[ni][r] = 0.f;
    float rs[2] = {0.f, 0.f};

    int qrow_frag = wid * 16 + (lane >> 2);
    int arow  = wid * 16 + (lane & 15);
    int acol8 = (lane >> 4) * 8;
    int brow  = (lane & 7) + ((lane >> 3) & 1) * 8;
    int bcol8 = (lane >> 4) * 8;
    int l4 = lane & 3;
    const float scale = 0.125f;

    int buf = 0;
    for (int it = 0; it < 5; it++) {
        int m0 = it * 64;
        if (it < 4) load_kv(m0 + 64, buf ^ 1);
        if (it < 4) asm volatile("cp.async.wait_group 1;");
        else        asm volatile("cp.async.wait_group 0;");
        __syncthreads();

        uint32_t sK = sK0 + buf * 64 * PB * 2;
        uint32_t sV = sV0 + buf * 64 * PB * 2;

        float sacc[8][4];
        #pragma unroll
        for (int ni = 0; ni < 8; ni++)
            #pragma unroll
            for (int r = 0; r < 4; r++) sacc[ni][r] = 0.f;
        #pragma unroll
        for (int kk = 0; kk < 4; kk++) {
            uint32_t a[4];
            uint32_t sa = sQ + (arow * PB + kk * 16 + acol8) * 2;
            asm volatile(
                "ldmatrix.sync.aligned.m8n8.x4.shared.b16 {%0,%1,%2,%3}, [%4];"
                : "=r"(a[0]), "=r"(a[1]), "=r"(a[2]), "=r"(a[3]) : "r"(sa));
            uint32_t bfr[4][4];
            #pragma unroll
            for (int t = 0; t < 4; t++) {
                uint32_t sbb = sK + ((t * 16 + brow) * PB + kk * 16 + bcol8) * 2;
                asm volatile(
                    "ldmatrix.sync.aligned.m8n8.x4.shared.b16 {%0,%1,%2,%3}, [%4];"
                    : "=r"(bfr[t][0]), "=r"(bfr[t][1]), "=r"(bfr[t][2]), "=r"(bfr[t][3])
                    : "r"(sbb));
            }
            #pragma unroll
            for (int ni = 0; ni < 8; ni++) {
                uint32_t b0 = bfr[ni >> 1][ni & 1];
                uint32_t b1 = bfr[ni >> 1][(ni & 1) + 2];
                asm volatile(
                    "mma.sync.aligned.m16n8k16.row.col.f32.f16.f16.f32 "
                    "{%0,%1,%2,%3}, {%4,%5,%6,%7}, {%8,%9}, {%0,%1,%2,%3};"
                    : "+f"(sacc[ni][0]), "+f"(sacc[ni][1]),
                      "+f"(sacc[ni][2]), "+f"(sacc[ni][3])
                    : "r"(a[0]), "r"(a[1]), "r"(a[2]), "r"(a[3]),
                      "r"(b0), "r"(b1));
            }
        }

        #pragma unroll
        for (int u = 0; u < 2; u++) {
            int rloc = qrow_frag + u * 8;
            int gr   = n0 + rloc;
            const float* mrow = mask + (size_t)(gr < N_ ? gr : 0) * MP + m0;
            float local = 0.f;
            #pragma unroll
            for (int ni = 0; ni < 8; ni++) {
                int c = ni * 8 + 2 * l4;
                float2 mv = *(const float2*)(mrow + c);
                float e0 = 0.f, e1 = 0.f;
                if (m0 + c     < N_) e0 = __expf(sacc[ni][2 * u + 0] * scale * mv.x);
                if (m0 + c + 1 < N_) e1 = __expf(sacc[ni][2 * u + 1] * scale * mv.y);
                local += e0 + e1;
                uint32_t pk = pack_f16x2(e0, e1);
                uint32_t pd = sP + (rloc * PB + c) * 2;
                asm volatile("st.shared.b32 [%0], %1;" :: "r"(pd), "r"(pk));
            }
            rs[u] += local;
        }
        __syncwarp();

        #pragma unroll
        for (int kk = 0; kk < 4; kk++) {
            uint32_t a[4];
            uint32_t sa = sP + (arow * PB + kk * 16 + acol8) * 2;
            asm volatile(
                "ldmatrix.sync.aligned.m8n8.x4.shared.b16 {%0,%1,%2,%3}, [%4];"
                : "=r"(a[0]), "=r"(a[1]), "=r"(a[2]), "=r"(a[3]) : "r"(sa));
            uint32_t bfr[4][4];
            #pragma unroll
            for (int t = 0; t < 4; t++) {
                uint32_t sbb = sV + ((kk * 16 + brow) * PB + t * 16 + bcol8) * 2;
                asm volatile(
                    "ldmatrix.sync.aligned.m8n8.x4.trans.shared.b16 {%0,%1,%2,%3}, [%4];"
                    : "=r"(bfr[t][0]), "=r"(bfr[t][1]), "=r"(bfr[t][2]), "=r"(bfr[t][3])
                    : "r"(sbb));
            }
            #pragma unroll
            for (int ni = 0; ni < 8; ni++) {
                uint32_t b0 = bfr[ni >> 1][(ni & 1) * 2];
                uint32_t b1 = bfr[ni >> 1][(ni & 1) * 2 + 1];
                asm volatile(
                    "mma.sync.aligned.m16n8k16.row.col.f32.f16.f16.f32 "
                    "{%0,%1,%2,%3}, {%4,%5,%6,%7}, {%8,%9}, {%0,%1,%2,%3};"
                    : "+f"(oacc[ni][0]), "+f"(oacc[ni][1]),
                      "+f"(oacc[ni][2]), "+f"(oacc[ni][3])
                    : "r"(a[0]), "r"(a[1]), "r"(a[2]), "r"(a[3]),
                      "r"(b0), "r"(b1));
            }
        }
        __syncthreads();
        buf ^= 1;
    }

    #pragma unroll
    for (int u = 0; u < 2; u++) {
        rs[u] += __shfl_xor_sync(0xffffffffu, rs[u], 1);
        rs[u] += __shfl_xor_sync(0xffffffffu, rs[u], 2);
        int gr = n0 + qrow_frag + u * 8;
        if (gr >= N_) continue;
        float inv = 1.f / rs[u];
        #pragma unroll
        for (int ni = 0; ni < 8; ni++) {
            int dc = ni * 8 + 2 * l4;
            float2 o = make_float2(oacc[ni][2 * u] * inv, oacc[ni][2 * u + 1] * inv);
            *(float2*)(out + gbase + (size_t)gr * D_ + dc) = o;
        }
    }
}

// ---------------- launch ----------------
extern "C" void kernel_launch(void* const* d_in, const int* in_sizes, int n_in,
                              void* d_out, int out_size)
{
    const float* query = (const float*)d_in[0];
    const float* key   = (const float*)d_in[1];
    const float* value = (const float*)d_in[2];
    const float* sem   = (const float*)d_in[3];
    const float* Wq    = (const float*)d_in[4];
    const float* bq    = (const float*)d_in[5];
    const float* Wk    = (const float*)d_in[6];
    const float* bk    = (const float*)d_in[7];
    const float* Wv    = (const float*)d_in[8];
    const float* bv    = (const float*)d_in[9];
    const float* Wo    = (const float*)d_in[10];
    const float* bo    = (const float*)d_in[11];
    float* out = (float*)d_out;

    float *mask_p, *attn_p;
    __half *qh_p, *kh_p, *vh_p, *wt_p;
    cudaGetSymbolAddress((void**)&mask_p, g_mask);
    cudaGetSymbolAddress((void**)&qh_p,   g_qh);
    cudaGetSymbolAddress((void**)&kh_p,   g_kh);
    cudaGetSymbolAddress((void**)&vh_p,   g_vh);
    cudaGetSymbolAddress((void**)&attn_p, g_attn);
    cudaGetSymbolAddress((void**)&wt_p,   g_wt);

    static bool attr_set = false;
    if (!attr_set) {
        cudaFuncSetAttribute(attn_mma_kernel,
                             cudaFuncAttributeMaxDynamicSharedMemorySize, ATTN_SMEM);
        cudaFuncSetAttribute(gemm_bias_f16_kernel,
                             cudaFuncAttributeMaxDynamicSharedMemorySize, GEMM_SMEM);
        attr_set = true;
    }

    mask_softmax_kernel<<<N_, 256>>>(sem, mask_p);

    dim3 tg(D_ / 32, D_ / 32, 4);
    transpose_w_kernel<<<tg, dim3(32, 8)>>>(Wq, Wk, Wv, Wo, wt_p);

    // fused Q/K/V projections -> fp16 outputs
    dim3 g3(D_ / 128, (M_TOT + 127) / 128, 3);
    gemm_bias_f16_kernel<<<g3, 256, GEMM_SMEM>>>(
        query, key, value, wt_p, bq, bk, bv, qh_p, kh_p, vh_p, M_TOT, 1);

    dim3 ga((N_ + 127) / 128, B_ * T_ * H_);
    attn_mma_kernel<<<ga, 256, ATTN_SMEM>>>(qh_p, kh_p, vh_p, mask_p, attn_p);

    // output projection (fp32 in/out)
    dim3 g1(D_ / 128, (M_TOT + 127) / 128, 1);
    gemm_bias_f16_kernel<<<g1, 256, GEMM_SMEM>>>(
        attn_p, attn_p, attn_p, wt_p + 3 * (size_t)D_ * D_, bo, bo, bo,
        out, out, out, M_TOT, 0);
}